// round 1
// baseline (speedup 1.0000x reference)
#include <cuda_runtime.h>
#include <math.h>

#define DM   1024
#define HD   64
#define NH   16
#define BATCH 2
#define SEQ  2048
#define NTOK (BATCH*SEQ)

// Scratch (no allocations allowed): Q, K, V projections and attention output.
__device__ float g_Q[NTOK*DM];
__device__ float g_K[NTOK*DM];
__device__ float g_V[NTOK*DM];
__device__ float g_O[NTOK*DM];

// ---------------------------------------------------------------------------
// C[m][n] = sum_k A[m][k] * B[n][k]   (A: [M,K] row-major, B: [N,K] row-major)
// 128x128 tile, BK=16, 256 threads, 8x8 per thread.
// ---------------------------------------------------------------------------
__global__ __launch_bounds__(256) void sgemm_nt(const float* __restrict__ A,
                                                const float* __restrict__ B,
                                                float* __restrict__ C,
                                                int M, int N, int K) {
    const int BM = 128, BN = 128, BK = 16;
    __shared__ float As[BK][BM + 4];
    __shared__ float Bs[BK][BN + 4];

    const int tid = threadIdx.x;
    const int bm = blockIdx.y * BM;
    const int bn = blockIdx.x * BN;
    const int tx = tid & 15;        // 0..15 -> 8 output cols each
    const int ty = tid >> 4;        // 0..15 -> 8 output rows each

    float acc[8][8];
#pragma unroll
    for (int i = 0; i < 8; i++)
#pragma unroll
        for (int j = 0; j < 8; j++) acc[i][j] = 0.f;

    for (int k0 = 0; k0 < K; k0 += BK) {
        // Cooperative load: 128 rows x 16 cols per operand = 512 float4 total.
#pragma unroll
        for (int i = 0; i < 2; i++) {
            int idx = tid + i * 256;
            int r = idx >> 2;
            int c = (idx & 3) << 2;
            float4 va = *(const float4*)(A + (size_t)(bm + r) * K + k0 + c);
            As[c + 0][r] = va.x; As[c + 1][r] = va.y;
            As[c + 2][r] = va.z; As[c + 3][r] = va.w;
            float4 vb = *(const float4*)(B + (size_t)(bn + r) * K + k0 + c);
            Bs[c + 0][r] = vb.x; Bs[c + 1][r] = vb.y;
            Bs[c + 2][r] = vb.z; Bs[c + 3][r] = vb.w;
        }
        __syncthreads();

#pragma unroll
        for (int kk = 0; kk < BK; kk++) {
            float a[8], b[8];
            *(float4*)(a)     = *(const float4*)&As[kk][ty * 8];
            *(float4*)(a + 4) = *(const float4*)&As[kk][ty * 8 + 4];
            *(float4*)(b)     = *(const float4*)&Bs[kk][tx * 8];
            *(float4*)(b + 4) = *(const float4*)&Bs[kk][tx * 8 + 4];
#pragma unroll
            for (int i = 0; i < 8; i++)
#pragma unroll
                for (int j = 0; j < 8; j++)
                    acc[i][j] = fmaf(a[i], b[j], acc[i][j]);
        }
        __syncthreads();
    }

#pragma unroll
    for (int i = 0; i < 8; i++) {
        float* cp = C + (size_t)(bm + ty * 8 + i) * N + bn + tx * 8;
        float4 o0 = make_float4(acc[i][0], acc[i][1], acc[i][2], acc[i][3]);
        float4 o1 = make_float4(acc[i][4], acc[i][5], acc[i][6], acc[i][7]);
        *(float4*)(cp)     = o0;
        *(float4*)(cp + 4) = o1;
    }
}

// ---------------------------------------------------------------------------
// Flash attention (fp32): one thread per query row, q + O accumulator in
// registers, K/V tiles of 16 keys staged in shared memory (broadcast reads).
// grid = (SEQ/128, NH, BATCH), block = 128.
// ---------------------------------------------------------------------------
#define TK 16

__global__ __launch_bounds__(128) void attn_kernel(const float* __restrict__ Q,
                                                   const float* __restrict__ K,
                                                   const float* __restrict__ V,
                                                   const int* __restrict__ mask,
                                                   float* __restrict__ O) {
    const int b = blockIdx.z;
    const int h = blockIdx.y;
    const int tid = threadIdx.x;
    const int q_row = blockIdx.x * 128 + tid;

    __shared__ float Ks[TK][HD];
    __shared__ float Vs[TK][HD];

    // Load my query row into registers (64 floats).
    const float* qp = Q + ((size_t)(b * SEQ + q_row)) * DM + h * HD;
    float q[HD];
#pragma unroll
    for (int d4 = 0; d4 < HD / 4; d4++) {
        float4 v = *(const float4*)(qp + d4 * 4);
        q[d4 * 4 + 0] = v.x; q[d4 * 4 + 1] = v.y;
        q[d4 * 4 + 2] = v.z; q[d4 * 4 + 3] = v.w;
    }

    float o[HD];
#pragma unroll
    for (int d = 0; d < HD; d++) o[d] = 0.f;
    float m = -INFINITY;
    float l = 0.f;

    const int* mrow = mask + ((size_t)(b * SEQ + q_row)) * SEQ;
    const float scale = 0.125f;   // 1/sqrt(64)

    for (int kt = 0; kt < SEQ / TK; kt++) {
        // Stage K/V tile: 16 rows x 64 floats = 256 float4 each; 2 per thread.
#pragma unroll
        for (int i = 0; i < 2; i++) {
            int idx = tid + i * 128;
            int r = idx >> 4;
            int c = (idx & 15) << 2;
            size_t goff = ((size_t)(b * SEQ + kt * TK + r)) * DM + h * HD + c;
            *(float4*)&Ks[r][c] = *(const float4*)(K + goff);
            *(float4*)&Vs[r][c] = *(const float4*)(V + goff);
        }
        __syncthreads();

        // Scores for my row vs 16 keys.
        float s[TK];
#pragma unroll
        for (int j = 0; j < TK; j++) {
            float acc = 0.f;
#pragma unroll
            for (int d4 = 0; d4 < HD / 4; d4++) {
                float4 kv = *(const float4*)&Ks[j][d4 * 4];
                acc = fmaf(q[d4 * 4 + 0], kv.x, acc);
                acc = fmaf(q[d4 * 4 + 1], kv.y, acc);
                acc = fmaf(q[d4 * 4 + 2], kv.z, acc);
                acc = fmaf(q[d4 * 4 + 3], kv.w, acc);
            }
            s[j] = acc * scale;
        }

        // Mask (int32, 0 -> -1e20).
#pragma unroll
        for (int j4 = 0; j4 < TK / 4; j4++) {
            int4 mm = *(const int4*)(mrow + kt * TK + j4 * 4);
            if (mm.x == 0) s[j4 * 4 + 0] = -1e20f;
            if (mm.y == 0) s[j4 * 4 + 1] = -1e20f;
            if (mm.z == 0) s[j4 * 4 + 2] = -1e20f;
            if (mm.w == 0) s[j4 * 4 + 3] = -1e20f;
        }

        // Online softmax update.
        float tmax = s[0];
#pragma unroll
        for (int j = 1; j < TK; j++) tmax = fmaxf(tmax, s[j]);
        float nm = fmaxf(m, tmax);
        float corr = __expf(m - nm);   // m=-INF first iter -> 0, no NaN (nm finite)
        float psum = 0.f;
#pragma unroll
        for (int j = 0; j < TK; j++) {
            s[j] = __expf(s[j] - nm);
            psum += s[j];
        }
        l = l * corr + psum;
        m = nm;

#pragma unroll
        for (int d = 0; d < HD; d++) o[d] *= corr;
#pragma unroll
        for (int j = 0; j < TK; j++) {
            float pj = s[j];
#pragma unroll
            for (int d4 = 0; d4 < HD / 4; d4++) {
                float4 vv = *(const float4*)&Vs[j][d4 * 4];
                o[d4 * 4 + 0] = fmaf(pj, vv.x, o[d4 * 4 + 0]);
                o[d4 * 4 + 1] = fmaf(pj, vv.y, o[d4 * 4 + 1]);
                o[d4 * 4 + 2] = fmaf(pj, vv.z, o[d4 * 4 + 2]);
                o[d4 * 4 + 3] = fmaf(pj, vv.w, o[d4 * 4 + 3]);
            }
        }
        __syncthreads();
    }

    const float inv_l = 1.f / l;
    float* op = O + ((size_t)(b * SEQ + q_row)) * DM + h * HD;
#pragma unroll
    for (int d4 = 0; d4 < HD / 4; d4++) {
        float4 v;
        v.x = o[d4 * 4 + 0] * inv_l;
        v.y = o[d4 * 4 + 1] * inv_l;
        v.z = o[d4 * 4 + 2] * inv_l;
        v.w = o[d4 * 4 + 3] * inv_l;
        *(float4*)(op + d4 * 4) = v;
    }
}

// ---------------------------------------------------------------------------
extern "C" void kernel_launch(void* const* d_in, const int* in_sizes, int n_in,
                              void* d_out, int out_size) {
    const float* query = (const float*)d_in[0];
    const float* key_t = (const float*)d_in[1];
    const float* value = (const float*)d_in[2];
    const int*   mask  = (const int*)d_in[3];
    const float* wq    = (const float*)d_in[4];
    const float* wk    = (const float*)d_in[5];
    const float* wv    = (const float*)d_in[6];
    const float* wo    = (const float*)d_in[7];
    float* out = (float*)d_out;

    float *Qp, *Kp, *Vp, *Op;
    cudaGetSymbolAddress((void**)&Qp, g_Q);
    cudaGetSymbolAddress((void**)&Kp, g_K);
    cudaGetSymbolAddress((void**)&Vp, g_V);
    cudaGetSymbolAddress((void**)&Op, g_O);

    dim3 gg(DM / 128, NTOK / 128);   // (8, 32)
    sgemm_nt<<<gg, 256>>>(query, wq, Qp, NTOK, DM, DM);
    sgemm_nt<<<gg, 256>>>(key_t, wk, Kp, NTOK, DM, DM);
    sgemm_nt<<<gg, 256>>>(value, wv, Vp, NTOK, DM, DM);

    dim3 ga(SEQ / 128, NH, BATCH);   // (16, 16, 2)
    attn_kernel<<<ga, 128>>>(Qp, Kp, Vp, mask, Op);

    sgemm_nt<<<gg, 256>>>(Op, wo, out, NTOK, DM, DM);
}

// round 2
// speedup vs baseline: 1.2078x; 1.2078x over previous
#include <cuda_runtime.h>
#include <cuda_bf16.h>
#include <math.h>
#include <stdint.h>

#define DM   1024
#define HD   64
#define NH   16
#define BATCH 2
#define SEQ  2048
#define NTOK (BATCH*SEQ)

// Scratch (no allocations allowed): Q, K, V projections and attention output.
__device__ float g_Q[NTOK*DM];
__device__ float g_K[NTOK*DM];
__device__ float g_V[NTOK*DM];
__device__ float g_O[NTOK*DM];

// ---------------------------------------------------------------------------
// Split-bf16 tensor-core GEMM:  C[m][n] = sum_k A[m][k]*B[n][k]
// A:[M,K] row-major, B:[N,K] row-major (Linear weight), M=4096, N=K=1024.
// fp32 operands split into bf16 hi+lo; 3x mma.sync m16n8k16 with fp32 accum
// recovers ~17 mantissa bits (rel err ~1e-5, far under the 1e-3 gate).
// Block tile 128x128, BK=32, 8 warps (2m x 4n), warp tile 64x32.
// ---------------------------------------------------------------------------
__device__ __forceinline__ void ldm4(uint32_t* r, uint32_t addr) {
    asm volatile("ldmatrix.sync.aligned.m8n8.x4.shared.b16 {%0,%1,%2,%3}, [%4];"
                 : "=r"(r[0]), "=r"(r[1]), "=r"(r[2]), "=r"(r[3]) : "r"(addr));
}

__device__ __forceinline__ void mma16816(float* c, const uint32_t* a, const uint32_t* b) {
    asm volatile(
        "mma.sync.aligned.m16n8k16.row.col.f32.bf16.bf16.f32 "
        "{%0,%1,%2,%3}, {%4,%5,%6,%7}, {%8,%9}, {%0,%1,%2,%3};\n"
        : "+f"(c[0]), "+f"(c[1]), "+f"(c[2]), "+f"(c[3])
        : "r"(a[0]), "r"(a[1]), "r"(a[2]), "r"(a[3]), "r"(b[0]), "r"(b[1]));
}

__global__ __launch_bounds__(256, 1) void gemm_bf16split(const float* __restrict__ A,
                                                         const float* __restrict__ B,
                                                         float* __restrict__ C) {
    constexpr int Kc = 1024, Nc = 1024, BK = 32, NK = Kc / BK;
    constexpr int LDS = 40;   // bf16 row stride: 32 + 8 pad -> conflict-free ldmatrix
    __shared__ __nv_bfloat16 sAh[128][LDS], sAl[128][LDS];
    __shared__ __nv_bfloat16 sBh[128][LDS], sBl[128][LDS];

    const int tid  = threadIdx.x;
    const int lane = tid & 31;
    const int warp = tid >> 5;
    const int wm = (warp & 1) * 64;      // warp row offset in block tile
    const int wn = (warp >> 1) * 32;     // warp col offset
    const int bm = blockIdx.y * 128;
    const int bn = blockIdx.x * 128;

    float acc[4][4][4];
#pragma unroll
    for (int i = 0; i < 4; i++)
#pragma unroll
        for (int j = 0; j < 4; j++)
#pragma unroll
            for (int v = 0; v < 4; v++) acc[i][j][v] = 0.f;

    float4 pa[4], pb[4];

    // --- gmem tile load into registers (128x32 fp32 per operand) ---
#define LOAD_TILE(k0)                                                          \
    {                                                                          \
        _Pragma("unroll")                                                      \
        for (int i = 0; i < 4; i++) {                                          \
            int lin = i * 256 + tid;                                           \
            int r = lin >> 3, c = (lin & 7) << 2;                              \
            pa[i] = *(const float4*)(A + (size_t)(bm + r) * Kc + (k0) + c);    \
            pb[i] = *(const float4*)(B + (size_t)(bn + r) * Kc + (k0) + c);    \
        }                                                                      \
    }

    // --- split fp32 -> bf16 hi/lo and store to smem ---
#define STORE_TILE()                                                           \
    {                                                                          \
        _Pragma("unroll")                                                      \
        for (int i = 0; i < 4; i++) {                                          \
            int lin = i * 256 + tid;                                           \
            int r = lin >> 3, c = (lin & 7) << 2;                              \
            float va[4] = {pa[i].x, pa[i].y, pa[i].z, pa[i].w};                \
            float vb[4] = {pb[i].x, pb[i].y, pb[i].z, pb[i].w};                \
            _Pragma("unroll")                                                  \
            for (int j = 0; j < 4; j++) {                                      \
                __nv_bfloat16 h = __float2bfloat16(va[j]);                     \
                sAh[r][c + j] = h;                                             \
                sAl[r][c + j] = __float2bfloat16(va[j] - __bfloat162float(h)); \
                __nv_bfloat16 g = __float2bfloat16(vb[j]);                     \
                sBh[r][c + j] = g;                                             \
                sBl[r][c + j] = __float2bfloat16(vb[j] - __bfloat162float(g)); \
            }                                                                  \
        }                                                                      \
    }

    LOAD_TILE(0);
    STORE_TILE();
    __syncthreads();

    for (int kt = 0; kt < NK; kt++) {
        if (kt + 1 < NK) LOAD_TILE((kt + 1) * BK);

#pragma unroll
        for (int kk = 0; kk < 2; kk++) {           // two k16 steps per BK=32
            uint32_t ah[4][4], al[4][4], bh[2][4], bl[2][4];
            const int acol = kk * 16 + (lane >> 4) * 8;
#pragma unroll
            for (int i = 0; i < 4; i++) {
                int arow = wm + i * 16 + (lane & 15);
                ldm4(ah[i], (uint32_t)__cvta_generic_to_shared(&sAh[arow][acol]));
                ldm4(al[i], (uint32_t)__cvta_generic_to_shared(&sAl[arow][acol]));
            }
            const int bcol = kk * 16 + ((lane >> 3) & 1) * 8;
            const int brow_off = (lane & 7) + (lane >> 4) * 8;
#pragma unroll
            for (int j2 = 0; j2 < 2; j2++) {
                int brow = wn + j2 * 16 + brow_off;
                ldm4(bh[j2], (uint32_t)__cvta_generic_to_shared(&sBh[brow][bcol]));
                ldm4(bl[j2], (uint32_t)__cvta_generic_to_shared(&sBl[brow][bcol]));
            }
#pragma unroll
            for (int i = 0; i < 4; i++)
#pragma unroll
                for (int j = 0; j < 4; j++) {
                    const uint32_t* bhp = &bh[j >> 1][(j & 1) * 2];
                    const uint32_t* blp = &bl[j >> 1][(j & 1) * 2];
                    mma16816(acc[i][j], ah[i], bhp);   // hi*hi
                    mma16816(acc[i][j], ah[i], blp);   // hi*lo
                    mma16816(acc[i][j], al[i], bhp);   // lo*hi
                }
        }
        __syncthreads();
        if (kt + 1 < NK) STORE_TILE();
        __syncthreads();
    }

    // Epilogue: fragment (g, t2) layout of m16n8 accumulators.
    const int g  = lane >> 2;
    const int t2 = (lane & 3) * 2;
#pragma unroll
    for (int i = 0; i < 4; i++)
#pragma unroll
        for (int j = 0; j < 4; j++) {
            int row = bm + wm + i * 16 + g;
            int col = bn + wn + j * 8 + t2;
            float2 lo = make_float2(acc[i][j][0], acc[i][j][1]);
            float2 hi = make_float2(acc[i][j][2], acc[i][j][3]);
            *(float2*)(C + (size_t)row * Nc + col)       = lo;
            *(float2*)(C + (size_t)(row + 8) * Nc + col) = hi;
        }
#undef LOAD_TILE
#undef STORE_TILE
}

// ---------------------------------------------------------------------------
// Flash attention (fp32): unchanged from R1 baseline (tensorized next round).
// ---------------------------------------------------------------------------
#define TK 16

__global__ __launch_bounds__(128) void attn_kernel(const float* __restrict__ Q,
                                                   const float* __restrict__ K,
                                                   const float* __restrict__ V,
                                                   const int* __restrict__ mask,
                                                   float* __restrict__ O) {
    const int b = blockIdx.z;
    const int h = blockIdx.y;
    const int tid = threadIdx.x;
    const int q_row = blockIdx.x * 128 + tid;

    __shared__ float Ks[TK][HD];
    __shared__ float Vs[TK][HD];

    const float* qp = Q + ((size_t)(b * SEQ + q_row)) * DM + h * HD;
    float q[HD];
#pragma unroll
    for (int d4 = 0; d4 < HD / 4; d4++) {
        float4 v = *(const float4*)(qp + d4 * 4);
        q[d4 * 4 + 0] = v.x; q[d4 * 4 + 1] = v.y;
        q[d4 * 4 + 2] = v.z; q[d4 * 4 + 3] = v.w;
    }

    float o[HD];
#pragma unroll
    for (int d = 0; d < HD; d++) o[d] = 0.f;
    float m = -INFINITY;
    float l = 0.f;

    const int* mrow = mask + ((size_t)(b * SEQ + q_row)) * SEQ;
    const float scale = 0.125f;

    for (int kt = 0; kt < SEQ / TK; kt++) {
#pragma unroll
        for (int i = 0; i < 2; i++) {
            int idx = tid + i * 128;
            int r = idx >> 4;
            int c = (idx & 15) << 2;
            size_t goff = ((size_t)(b * SEQ + kt * TK + r)) * DM + h * HD + c;
            *(float4*)&Ks[r][c] = *(const float4*)(K + goff);
            *(float4*)&Vs[r][c] = *(const float4*)(V + goff);
        }
        __syncthreads();

        float s[TK];
#pragma unroll
        for (int j = 0; j < TK; j++) {
            float acc = 0.f;
#pragma unroll
            for (int d4 = 0; d4 < HD / 4; d4++) {
                float4 kv = *(const float4*)&Ks[j][d4 * 4];
                acc = fmaf(q[d4 * 4 + 0], kv.x, acc);
                acc = fmaf(q[d4 * 4 + 1], kv.y, acc);
                acc = fmaf(q[d4 * 4 + 2], kv.z, acc);
                acc = fmaf(q[d4 * 4 + 3], kv.w, acc);
            }
            s[j] = acc * scale;
        }

#pragma unroll
        for (int j4 = 0; j4 < TK / 4; j4++) {
            int4 mm = *(const int4*)(mrow + kt * TK + j4 * 4);
            if (mm.x == 0) s[j4 * 4 + 0] = -1e20f;
            if (mm.y == 0) s[j4 * 4 + 1] = -1e20f;
            if (mm.z == 0) s[j4 * 4 + 2] = -1e20f;
            if (mm.w == 0) s[j4 * 4 + 3] = -1e20f;
        }

        float tmax = s[0];
#pragma unroll
        for (int j = 1; j < TK; j++) tmax = fmaxf(tmax, s[j]);
        float nm = fmaxf(m, tmax);
        float corr = __expf(m - nm);
        float psum = 0.f;
#pragma unroll
        for (int j = 0; j < TK; j++) {
            s[j] = __expf(s[j] - nm);
            psum += s[j];
        }
        l = l * corr + psum;
        m = nm;

#pragma unroll
        for (int d = 0; d < HD; d++) o[d] *= corr;
#pragma unroll
        for (int j = 0; j < TK; j++) {
            float pj = s[j];
#pragma unroll
            for (int d4 = 0; d4 < HD / 4; d4++) {
                float4 vv = *(const float4*)&Vs[j][d4 * 4];
                o[d4 * 4 + 0] = fmaf(pj, vv.x, o[d4 * 4 + 0]);
                o[d4 * 4 + 1] = fmaf(pj, vv.y, o[d4 * 4 + 1]);
                o[d4 * 4 + 2] = fmaf(pj, vv.z, o[d4 * 4 + 2]);
                o[d4 * 4 + 3] = fmaf(pj, vv.w, o[d4 * 4 + 3]);
            }
        }
        __syncthreads();
    }

    const float inv_l = 1.f / l;
    float* op = O + ((size_t)(b * SEQ + q_row)) * DM + h * HD;
#pragma unroll
    for (int d4 = 0; d4 < HD / 4; d4++) {
        float4 v;
        v.x = o[d4 * 4 + 0] * inv_l;
        v.y = o[d4 * 4 + 1] * inv_l;
        v.z = o[d4 * 4 + 2] * inv_l;
        v.w = o[d4 * 4 + 3] * inv_l;
        *(float4*)(op + d4 * 4) = v;
    }
}

// ---------------------------------------------------------------------------
extern "C" void kernel_launch(void* const* d_in, const int* in_sizes, int n_in,
                              void* d_out, int out_size) {
    const float* query = (const float*)d_in[0];
    const float* key_t = (const float*)d_in[1];
    const float* value = (const float*)d_in[2];
    const int*   mask  = (const int*)d_in[3];
    const float* wq    = (const float*)d_in[4];
    const float* wk    = (const float*)d_in[5];
    const float* wv    = (const float*)d_in[6];
    const float* wo    = (const float*)d_in[7];
    float* out = (float*)d_out;

    float *Qp, *Kp, *Vp, *Op;
    cudaGetSymbolAddress((void**)&Qp, g_Q);
    cudaGetSymbolAddress((void**)&Kp, g_K);
    cudaGetSymbolAddress((void**)&Vp, g_V);
    cudaGetSymbolAddress((void**)&Op, g_O);

    dim3 gg(DM / 128, NTOK / 128);   // (8, 32)
    gemm_bf16split<<<gg, 256>>>(query, wq, Qp);
    gemm_bf16split<<<gg, 256>>>(key_t, wk, Kp);
    gemm_bf16split<<<gg, 256>>>(value, wv, Vp);

    dim3 ga(SEQ / 128, NH, BATCH);   // (16, 16, 2)
    attn_kernel<<<ga, 128>>>(Qp, Kp, Vp, mask, Op);

    gemm_bf16split<<<gg, 256>>>(Op, wo, out);
}

// round 3
// speedup vs baseline: 2.4369x; 2.0177x over previous
#include <cuda_runtime.h>
#include <cuda_bf16.h>
#include <math.h>
#include <stdint.h>

#define DM   1024
#define HD   64
#define NH   16
#define BATCH 2
#define SEQ  2048
#define NTOK (BATCH*SEQ)
#define MWORDS (BATCH*SEQ*SEQ/32)

// Scratch (no allocations allowed).
__device__ __nv_bfloat16 g_Qh[NTOK*DM], g_Ql[NTOK*DM];
__device__ __nv_bfloat16 g_Kh[NTOK*DM], g_Kl[NTOK*DM];
__device__ __nv_bfloat16 g_Vh[NTOK*DM], g_Vl[NTOK*DM];
__device__ float g_O[NTOK*DM];
__device__ uint32_t g_Mb[MWORDS];

// ---------------------------------------------------------------------------
// Helpers
// ---------------------------------------------------------------------------
__device__ __forceinline__ void ldm4(uint32_t* r, uint32_t addr) {
    asm volatile("ldmatrix.sync.aligned.m8n8.x4.shared.b16 {%0,%1,%2,%3}, [%4];"
                 : "=r"(r[0]), "=r"(r[1]), "=r"(r[2]), "=r"(r[3]) : "r"(addr));
}
__device__ __forceinline__ void ldm4t(uint32_t* r, uint32_t addr) {
    asm volatile("ldmatrix.sync.aligned.m8n8.x4.trans.shared.b16 {%0,%1,%2,%3}, [%4];"
                 : "=r"(r[0]), "=r"(r[1]), "=r"(r[2]), "=r"(r[3]) : "r"(addr));
}
__device__ __forceinline__ void mma16816(float* c, const uint32_t* a, const uint32_t* b) {
    asm volatile(
        "mma.sync.aligned.m16n8k16.row.col.f32.bf16.bf16.f32 "
        "{%0,%1,%2,%3}, {%4,%5,%6,%7}, {%8,%9}, {%0,%1,%2,%3};\n"
        : "+f"(c[0]), "+f"(c[1]), "+f"(c[2]), "+f"(c[3])
        : "r"(a[0]), "r"(a[1]), "r"(a[2]), "r"(a[3]), "r"(b[0]), "r"(b[1]));
}
__device__ __forceinline__ uint32_t bf2pack(float lo, float hi) {
    unsigned short l = __bfloat16_as_ushort(__float2bfloat16_rn(lo));
    unsigned short h = __bfloat16_as_ushort(__float2bfloat16_rn(hi));
    return ((uint32_t)h << 16) | (uint32_t)l;
}
__device__ __forceinline__ float bf16res(float x) {
    return x - __bfloat162float(__float2bfloat16_rn(x));
}

// ---------------------------------------------------------------------------
// Mask -> bitmask (1 bit per element), ballot per warp.
// ---------------------------------------------------------------------------
__global__ __launch_bounds__(256) void pack_mask(const int* __restrict__ mask,
                                                 uint32_t* __restrict__ bits) {
    int t = blockIdx.x * blockDim.x + threadIdx.x;
    unsigned bal = __ballot_sync(0xffffffffu, mask[t] != 0);
    if ((t & 31) == 0) bits[t >> 5] = bal;
}

// ---------------------------------------------------------------------------
// Split-bf16 tensor-core GEMM:  C[m][n] = sum_k A[m][k]*B[n][k]
// PLANES=1: write bf16 hi/lo planes (scaled); PLANES=0: write fp32 C.
// ---------------------------------------------------------------------------
template<int PLANES>
__global__ __launch_bounds__(256, 1) void gemm_bf16split(const float* __restrict__ A,
                                                         const float* __restrict__ B,
                                                         float* __restrict__ C,
                                                         __nv_bfloat16* __restrict__ Ch,
                                                         __nv_bfloat16* __restrict__ Cl,
                                                         float scale) {
    constexpr int Kc = 1024, Nc = 1024, BK = 32, NK = Kc / BK;
    constexpr int LDSg = 40;
    __shared__ __nv_bfloat16 sAh[128][LDSg], sAl[128][LDSg];
    __shared__ __nv_bfloat16 sBh[128][LDSg], sBl[128][LDSg];

    const int tid  = threadIdx.x;
    const int lane = tid & 31;
    const int warp = tid >> 5;
    const int wm = (warp & 1) * 64;
    const int wn = (warp >> 1) * 32;
    const int bm = blockIdx.y * 128;
    const int bn = blockIdx.x * 128;

    float acc[4][4][4];
#pragma unroll
    for (int i = 0; i < 4; i++)
#pragma unroll
        for (int j = 0; j < 4; j++)
#pragma unroll
            for (int v = 0; v < 4; v++) acc[i][j][v] = 0.f;

    float4 pa[4], pb[4];

#define LOAD_TILE(k0)                                                          \
    {                                                                          \
        _Pragma("unroll")                                                      \
        for (int i = 0; i < 4; i++) {                                          \
            int lin = i * 256 + tid;                                           \
            int r = lin >> 3, c = (lin & 7) << 2;                              \
            pa[i] = *(const float4*)(A + (size_t)(bm + r) * Kc + (k0) + c);    \
            pb[i] = *(const float4*)(B + (size_t)(bn + r) * Kc + (k0) + c);    \
        }                                                                      \
    }
#define STORE_TILE()                                                           \
    {                                                                          \
        _Pragma("unroll")                                                      \
        for (int i = 0; i < 4; i++) {                                          \
            int lin = i * 256 + tid;                                           \
            int r = lin >> 3, c = (lin & 7) << 2;                              \
            float va[4] = {pa[i].x, pa[i].y, pa[i].z, pa[i].w};                \
            float vb[4] = {pb[i].x, pb[i].y, pb[i].z, pb[i].w};                \
            _Pragma("unroll")                                                  \
            for (int j = 0; j < 4; j++) {                                      \
                __nv_bfloat16 h = __float2bfloat16(va[j]);                     \
                sAh[r][c + j] = h;                                             \
                sAl[r][c + j] = __float2bfloat16(va[j] - __bfloat162float(h)); \
                __nv_bfloat16 g2 = __float2bfloat16(vb[j]);                    \
                sBh[r][c + j] = g2;                                            \
                sBl[r][c + j] = __float2bfloat16(vb[j] - __bfloat162float(g2));\
            }                                                                  \
        }                                                                      \
    }

    LOAD_TILE(0);
    STORE_TILE();
    __syncthreads();

    for (int kt = 0; kt < NK; kt++) {
        if (kt + 1 < NK) LOAD_TILE((kt + 1) * BK);

#pragma unroll
        for (int kk = 0; kk < 2; kk++) {
            uint32_t ah[4][4], al[4][4], bh[2][4], bl[2][4];
            const int acol = kk * 16 + (lane >> 4) * 8;
#pragma unroll
            for (int i = 0; i < 4; i++) {
                int arow = wm + i * 16 + (lane & 15);
                ldm4(ah[i], (uint32_t)__cvta_generic_to_shared(&sAh[arow][acol]));
                ldm4(al[i], (uint32_t)__cvta_generic_to_shared(&sAl[arow][acol]));
            }
            const int bcol = kk * 16 + ((lane >> 3) & 1) * 8;
            const int brow_off = (lane & 7) + (lane >> 4) * 8;
#pragma unroll
            for (int j2 = 0; j2 < 2; j2++) {
                int brow = wn + j2 * 16 + brow_off;
                ldm4(bh[j2], (uint32_t)__cvta_generic_to_shared(&sBh[brow][bcol]));
                ldm4(bl[j2], (uint32_t)__cvta_generic_to_shared(&sBl[brow][bcol]));
            }
#pragma unroll
            for (int i = 0; i < 4; i++)
#pragma unroll
                for (int j = 0; j < 4; j++) {
                    const uint32_t* bhp = &bh[j >> 1][(j & 1) * 2];
                    const uint32_t* blp = &bl[j >> 1][(j & 1) * 2];
                    mma16816(acc[i][j], ah[i], bhp);
                    mma16816(acc[i][j], ah[i], blp);
                    mma16816(acc[i][j], al[i], bhp);
                }
        }
        __syncthreads();
        if (kt + 1 < NK) STORE_TILE();
        __syncthreads();
    }

    const int g  = lane >> 2;
    const int t2 = (lane & 3) * 2;
#pragma unroll
    for (int i = 0; i < 4; i++)
#pragma unroll
        for (int j = 0; j < 4; j++) {
            int row = bm + wm + i * 16 + g;
            int col = bn + wn + j * 8 + t2;
            if (PLANES) {
                size_t i0 = (size_t)row * Nc + col;
                size_t i1 = (size_t)(row + 8) * Nc + col;
                float v0 = acc[i][j][0] * scale, v1 = acc[i][j][1] * scale;
                float v2 = acc[i][j][2] * scale, v3 = acc[i][j][3] * scale;
                *(uint32_t*)(Ch + i0) = bf2pack(v0, v1);
                *(uint32_t*)(Cl + i0) = bf2pack(bf16res(v0), bf16res(v1));
                *(uint32_t*)(Ch + i1) = bf2pack(v2, v3);
                *(uint32_t*)(Cl + i1) = bf2pack(bf16res(v2), bf16res(v3));
            } else {
                *(float2*)(C + (size_t)row * Nc + col) =
                    make_float2(acc[i][j][0], acc[i][j][1]);
                *(float2*)(C + (size_t)(row + 8) * Nc + col) =
                    make_float2(acc[i][j][2], acc[i][j][3]);
            }
        }
#undef LOAD_TILE
#undef STORE_TILE
}

// ---------------------------------------------------------------------------
// Tensor-core flash attention (split-bf16, fp32 accum).
// Block: 64 q-rows x one head; 4 warps (16 rows each); K/V tiles of 64 keys.
// Q pre-scaled by 1/8 at projection time.
// ---------------------------------------------------------------------------
#define LDA 72   // 64 + 8 pad (bf16) -> conflict-free ldmatrix

__global__ __launch_bounds__(128) void attn_mma(
    const __nv_bfloat16* __restrict__ Qh, const __nv_bfloat16* __restrict__ Ql,
    const __nv_bfloat16* __restrict__ Kh, const __nv_bfloat16* __restrict__ Kl,
    const __nv_bfloat16* __restrict__ Vh, const __nv_bfloat16* __restrict__ Vl,
    const uint32_t* __restrict__ Mb, float* __restrict__ O) {
    __shared__ __nv_bfloat16 sKh[64][LDA], sKl[64][LDA];
    __shared__ __nv_bfloat16 sVh[64][LDA], sVl[64][LDA];

    const int b = blockIdx.z, h = blockIdx.y;
    const int q0 = blockIdx.x * 64;
    const int tid = threadIdx.x, lane = tid & 31, warp = tid >> 5;
    const int g = lane >> 2, t2 = (lane & 3) * 2;

    // Stage Q (reuse K buffers), load A fragments.
    for (int idx = tid; idx < 512; idx += 128) {
        int r = idx >> 3, c = (idx & 7) * 8;
        size_t go = (size_t)(b * SEQ + q0 + r) * DM + h * HD + c;
        *(uint4*)&sKh[r][c] = *(const uint4*)(Qh + go);
        *(uint4*)&sKl[r][c] = *(const uint4*)(Ql + go);
    }
    __syncthreads();
    uint32_t qh[4][4], ql[4][4];
    {
        int arow = warp * 16 + (lane & 15);
#pragma unroll
        for (int kk = 0; kk < 4; kk++) {
            int acol = kk * 16 + (lane >> 4) * 8;
            ldm4(qh[kk], (uint32_t)__cvta_generic_to_shared(&sKh[arow][acol]));
            ldm4(ql[kk], (uint32_t)__cvta_generic_to_shared(&sKl[arow][acol]));
        }
    }
    __syncthreads();

    float oa[8][4];
#pragma unroll
    for (int j = 0; j < 8; j++)
#pragma unroll
        for (int v = 0; v < 4; v++) oa[j][v] = 0.f;
    float mx0 = -INFINITY, mx1 = -INFINITY, l0 = 0.f, l1 = 0.f;

    const uint32_t* mr0 = Mb + (size_t)(b * SEQ + q0 + warp * 16 + g) * (SEQ / 32);
    const uint32_t* mr1 = mr0 + 8 * (SEQ / 32);

    for (int kt = 0; kt < SEQ / 64; kt++) {
        for (int idx = tid; idx < 512; idx += 128) {
            int r = idx >> 3, c = (idx & 7) * 8;
            size_t go = (size_t)(b * SEQ + kt * 64 + r) * DM + h * HD + c;
            *(uint4*)&sKh[r][c] = *(const uint4*)(Kh + go);
            *(uint4*)&sKl[r][c] = *(const uint4*)(Kl + go);
            *(uint4*)&sVh[r][c] = *(const uint4*)(Vh + go);
            *(uint4*)&sVl[r][c] = *(const uint4*)(Vl + go);
        }
        __syncthreads();

        // S = Q K^T (scores; scale already folded into Q)
        float s[8][4];
#pragma unroll
        for (int j = 0; j < 8; j++)
#pragma unroll
            for (int v = 0; v < 4; v++) s[j][v] = 0.f;
#pragma unroll
        for (int kk = 0; kk < 4; kk++) {
            uint32_t bh[4][4], bl[4][4];
            const int bro = (lane & 7) + (lane >> 4) * 8;
            const int bco = kk * 16 + ((lane >> 3) & 1) * 8;
#pragma unroll
            for (int j2 = 0; j2 < 4; j2++) {
                ldm4(bh[j2], (uint32_t)__cvta_generic_to_shared(&sKh[j2 * 16 + bro][bco]));
                ldm4(bl[j2], (uint32_t)__cvta_generic_to_shared(&sKl[j2 * 16 + bro][bco]));
            }
#pragma unroll
            for (int j = 0; j < 8; j++) {
                const uint32_t* bhp = &bh[j >> 1][(j & 1) * 2];
                const uint32_t* blp = &bl[j >> 1][(j & 1) * 2];
                mma16816(s[j], qh[kk], bhp);
                mma16816(s[j], qh[kk], blp);
                mma16816(s[j], ql[kk], bhp);
            }
        }

        // Mask via bitmask words.
        uint32_t w0a = mr0[kt * 2], w0b = mr0[kt * 2 + 1];
        uint32_t w1a = mr1[kt * 2], w1b = mr1[kt * 2 + 1];
#pragma unroll
        for (int j = 0; j < 8; j++) {
            uint32_t wr0 = (j < 4) ? w0a : w0b;
            uint32_t wr1 = (j < 4) ? w1a : w1b;
            int sh = (j * 8 + t2) & 31;
            if (!((wr0 >> sh) & 1u))       s[j][0] = -1e20f;
            if (!((wr0 >> (sh + 1)) & 1u)) s[j][1] = -1e20f;
            if (!((wr1 >> sh) & 1u))       s[j][2] = -1e20f;
            if (!((wr1 >> (sh + 1)) & 1u)) s[j][3] = -1e20f;
        }

        // Online softmax (rows g / g+8 per lane, quad reductions).
        float tm0 = s[0][0], tm1 = s[0][2];
#pragma unroll
        for (int j = 0; j < 8; j++) {
            tm0 = fmaxf(tm0, fmaxf(s[j][0], s[j][1]));
            tm1 = fmaxf(tm1, fmaxf(s[j][2], s[j][3]));
        }
        tm0 = fmaxf(tm0, __shfl_xor_sync(0xffffffffu, tm0, 1));
        tm0 = fmaxf(tm0, __shfl_xor_sync(0xffffffffu, tm0, 2));
        tm1 = fmaxf(tm1, __shfl_xor_sync(0xffffffffu, tm1, 1));
        tm1 = fmaxf(tm1, __shfl_xor_sync(0xffffffffu, tm1, 2));
        float nm0 = fmaxf(mx0, tm0), nm1 = fmaxf(mx1, tm1);
        float cr0 = __expf(mx0 - nm0), cr1 = __expf(mx1 - nm1);
        mx0 = nm0; mx1 = nm1;

        float ps0 = 0.f, ps1 = 0.f;
#pragma unroll
        for (int j = 0; j < 8; j++) {
            s[j][0] = __expf(s[j][0] - nm0); ps0 += s[j][0];
            s[j][1] = __expf(s[j][1] - nm0); ps0 += s[j][1];
            s[j][2] = __expf(s[j][2] - nm1); ps1 += s[j][2];
            s[j][3] = __expf(s[j][3] - nm1); ps1 += s[j][3];
        }
        ps0 += __shfl_xor_sync(0xffffffffu, ps0, 1);
        ps0 += __shfl_xor_sync(0xffffffffu, ps0, 2);
        ps1 += __shfl_xor_sync(0xffffffffu, ps1, 1);
        ps1 += __shfl_xor_sync(0xffffffffu, ps1, 2);
        l0 = l0 * cr0 + ps0;
        l1 = l1 * cr1 + ps1;
#pragma unroll
        for (int j = 0; j < 8; j++) {
            oa[j][0] *= cr0; oa[j][1] *= cr0;
            oa[j][2] *= cr1; oa[j][3] *= cr1;
        }

        // Repack P (C-frag) -> A-frags, split hi/lo.
        uint32_t ph[4][4], pl[4][4];
#pragma unroll
        for (int s4 = 0; s4 < 4; s4++) {
            int ta = 2 * s4, tb = ta + 1;
            ph[s4][0] = bf2pack(s[ta][0], s[ta][1]);
            ph[s4][1] = bf2pack(s[ta][2], s[ta][3]);
            ph[s4][2] = bf2pack(s[tb][0], s[tb][1]);
            ph[s4][3] = bf2pack(s[tb][2], s[tb][3]);
            pl[s4][0] = bf2pack(bf16res(s[ta][0]), bf16res(s[ta][1]));
            pl[s4][1] = bf2pack(bf16res(s[ta][2]), bf16res(s[ta][3]));
            pl[s4][2] = bf2pack(bf16res(s[tb][0]), bf16res(s[tb][1]));
            pl[s4][3] = bf2pack(bf16res(s[tb][2]), bf16res(s[tb][3]));
        }

        // O += P V  (V^T fragments via ldmatrix.trans)
#pragma unroll
        for (int s4 = 0; s4 < 4; s4++) {
            uint32_t vh[4][4], vl[4][4];
            const int vrow = s4 * 16 + ((lane >> 3) & 1) * 8 + (lane & 7);
#pragma unroll
            for (int n2 = 0; n2 < 4; n2++) {
                int vcol = n2 * 16 + (lane >> 4) * 8;
                ldm4t(vh[n2], (uint32_t)__cvta_generic_to_shared(&sVh[vrow][vcol]));
                ldm4t(vl[n2], (uint32_t)__cvta_generic_to_shared(&sVl[vrow][vcol]));
            }
#pragma unroll
            for (int j = 0; j < 8; j++) {
                const uint32_t* bhp = &vh[j >> 1][(j & 1) * 2];
                const uint32_t* blp = &vl[j >> 1][(j & 1) * 2];
                mma16816(oa[j], ph[s4], bhp);
                mma16816(oa[j], ph[s4], blp);
                mma16816(oa[j], pl[s4], bhp);
            }
        }
        __syncthreads();
    }

    // Epilogue: normalize and store fp32.
    float il0 = 1.f / l0, il1 = 1.f / l1;
    int row0 = b * SEQ + q0 + warp * 16 + g;
    float* o0 = O + (size_t)row0 * DM + h * HD;
    float* o1 = o0 + (size_t)8 * DM;
#pragma unroll
    for (int j = 0; j < 8; j++) {
        *(float2*)(o0 + j * 8 + t2) = make_float2(oa[j][0] * il0, oa[j][1] * il0);
        *(float2*)(o1 + j * 8 + t2) = make_float2(oa[j][2] * il1, oa[j][3] * il1);
    }
}

// ---------------------------------------------------------------------------
extern "C" void kernel_launch(void* const* d_in, const int* in_sizes, int n_in,
                              void* d_out, int out_size) {
    const float* query = (const float*)d_in[0];
    const float* key_t = (const float*)d_in[1];
    const float* value = (const float*)d_in[2];
    const int*   mask  = (const int*)d_in[3];
    const float* wq    = (const float*)d_in[4];
    const float* wk    = (const float*)d_in[5];
    const float* wv    = (const float*)d_in[6];
    const float* wo    = (const float*)d_in[7];
    float* out = (float*)d_out;

    __nv_bfloat16 *Qh, *Ql, *Kh, *Kl, *Vh, *Vl;
    float* Op;
    uint32_t* Mb;
    cudaGetSymbolAddress((void**)&Qh, g_Qh);
    cudaGetSymbolAddress((void**)&Ql, g_Ql);
    cudaGetSymbolAddress((void**)&Kh, g_Kh);
    cudaGetSymbolAddress((void**)&Kl, g_Kl);
    cudaGetSymbolAddress((void**)&Vh, g_Vh);
    cudaGetSymbolAddress((void**)&Vl, g_Vl);
    cudaGetSymbolAddress((void**)&Op, g_O);
    cudaGetSymbolAddress((void**)&Mb, g_Mb);

    pack_mask<<<MWORDS * 32 / 256, 256>>>(mask, Mb);

    dim3 gg(DM / 128, NTOK / 128);   // (8, 32)
    gemm_bf16split<1><<<gg, 256>>>(query, wq, nullptr, Qh, Ql, 0.125f);
    gemm_bf16split<1><<<gg, 256>>>(key_t, wk, nullptr, Kh, Kl, 1.0f);
    gemm_bf16split<1><<<gg, 256>>>(value, wv, nullptr, Vh, Vl, 1.0f);

    dim3 ga(SEQ / 64, NH, BATCH);    // (32, 16, 2)
    attn_mma<<<ga, 128>>>(Qh, Ql, Kh, Kl, Vh, Vl, Mb, Op);

    gemm_bf16split<0><<<gg, 256>>>(Op, wo, out, nullptr, nullptr, 1.0f);
}

// round 5
// speedup vs baseline: 2.4429x; 1.0025x over previous
#include <cuda_runtime.h>
#include <cuda_bf16.h>
#include <math.h>
#include <stdint.h>

#define DM   1024
#define HD   64
#define NH   16
#define BATCH 2
#define SEQ  2048
#define NTOK (BATCH*SEQ)
#define MWORDS (BATCH*SEQ*SEQ/32)

// ---------------------------------------------------------------------------
// Scratch (no allocations allowed).
// ---------------------------------------------------------------------------
__device__ __nv_bfloat16 g_iQh[NTOK*DM], g_iQl[NTOK*DM];   // input planes
__device__ __nv_bfloat16 g_iKh[NTOK*DM], g_iKl[NTOK*DM];
__device__ __nv_bfloat16 g_iVh[NTOK*DM], g_iVl[NTOK*DM];
__device__ __nv_bfloat16 g_wqh[DM*DM], g_wql[DM*DM];       // weight planes
__device__ __nv_bfloat16 g_wkh[DM*DM], g_wkl[DM*DM];
__device__ __nv_bfloat16 g_wvh[DM*DM], g_wvl[DM*DM];
__device__ __nv_bfloat16 g_woh[DM*DM], g_wol[DM*DM];
__device__ __nv_bfloat16 g_Qh[NTOK*DM], g_Ql[NTOK*DM];     // projected planes
__device__ __nv_bfloat16 g_Kh[NTOK*DM], g_Kl[NTOK*DM];
__device__ __nv_bfloat16 g_Vh[NTOK*DM], g_Vl[NTOK*DM];
__device__ __nv_bfloat16 g_Oh[NTOK*DM], g_Ol[NTOK*DM];     // attention output planes
__device__ uint32_t g_Mb[MWORDS];

// ---------------------------------------------------------------------------
// Helpers
// ---------------------------------------------------------------------------
__device__ __forceinline__ uint32_t smem_u32(const void* p) {
    uint32_t a;
    asm("{ .reg .u64 t; cvta.to.shared.u64 t, %1; cvt.u32.u64 %0, t; }" : "=r"(a) : "l"(p));
    return a;
}
__device__ __forceinline__ uint32_t bf2pack(float lo, float hi) {
    unsigned short l = __bfloat16_as_ushort(__float2bfloat16_rn(lo));
    unsigned short h = __bfloat16_as_ushort(__float2bfloat16_rn(hi));
    return ((uint32_t)h << 16) | (uint32_t)l;
}
__device__ __forceinline__ float bf16res(float x) {
    return x - __bfloat162float(__float2bfloat16_rn(x));
}
__device__ __forceinline__ void ldm4(uint32_t* r, uint32_t addr) {
    asm volatile("ldmatrix.sync.aligned.m8n8.x4.shared.b16 {%0,%1,%2,%3}, [%4];"
                 : "=r"(r[0]), "=r"(r[1]), "=r"(r[2]), "=r"(r[3]) : "r"(addr));
}
__device__ __forceinline__ void ldm4t(uint32_t* r, uint32_t addr) {
    asm volatile("ldmatrix.sync.aligned.m8n8.x4.trans.shared.b16 {%0,%1,%2,%3}, [%4];"
                 : "=r"(r[0]), "=r"(r[1]), "=r"(r[2]), "=r"(r[3]) : "r"(addr));
}
__device__ __forceinline__ void mma16816(float* c, const uint32_t* a, const uint32_t* b) {
    asm volatile(
        "mma.sync.aligned.m16n8k16.row.col.f32.bf16.bf16.f32 "
        "{%0,%1,%2,%3}, {%4,%5,%6,%7}, {%8,%9}, {%0,%1,%2,%3};\n"
        : "+f"(c[0]), "+f"(c[1]), "+f"(c[2]), "+f"(c[3])
        : "r"(a[0]), "r"(a[1]), "r"(a[2]), "r"(a[3]), "r"(b[0]), "r"(b[1]));
}
__device__ __forceinline__ void cpa16(uint32_t dst, const void* src) {
    asm volatile("cp.async.cg.shared.global [%0], [%1], 16;" :: "r"(dst), "l"(src) : "memory");
}
__device__ __forceinline__ void cpa_commit() { asm volatile("cp.async.commit_group;" ::: "memory"); }
__device__ __forceinline__ void cpa_wait1()  { asm volatile("cp.async.wait_group 1;" ::: "memory"); }
__device__ __forceinline__ void cpa_wait0()  { asm volatile("cp.async.wait_group 0;" ::: "memory"); }

// ---------------------------------------------------------------------------
// Mask -> bitmask
// ---------------------------------------------------------------------------
__global__ __launch_bounds__(256) void pack_mask(const int* __restrict__ mask,
                                                 uint32_t* __restrict__ bits) {
    int t = blockIdx.x * blockDim.x + threadIdx.x;
    unsigned bal = __ballot_sync(0xffffffffu, mask[t] != 0);
    if ((t & 31) == 0) bits[t >> 5] = bal;
}

// ---------------------------------------------------------------------------
// fp32 -> bf16 hi/lo planes (elementwise)
// ---------------------------------------------------------------------------
__global__ __launch_bounds__(256) void conv_split(const float* __restrict__ x,
                                                  __nv_bfloat16* __restrict__ xh,
                                                  __nv_bfloat16* __restrict__ xl) {
    int t = blockIdx.x * blockDim.x + threadIdx.x;
    float4 v = ((const float4*)x)[t];
    uint32_t h0 = bf2pack(v.x, v.y), h1 = bf2pack(v.z, v.w);
    uint32_t l0 = bf2pack(bf16res(v.x), bf16res(v.y));
    uint32_t l1 = bf2pack(bf16res(v.z), bf16res(v.w));
    ((uint2*)xh)[t] = make_uint2(h0, h1);
    ((uint2*)xl)[t] = make_uint2(l0, l1);
}

// ---------------------------------------------------------------------------
// Split-bf16 mma.sync GEMM on pre-split planes:
//   C[m][n] = sum_k A[m][k]*B[n][k]     (both operands K-major, K=1024)
// Tile 128x128, BK=32, cp.async double-buffered, 8 warps (2m x 4n), 64x32/warp.
// PLANES=1: epilogue writes bf16 hi/lo planes (scaled). PLANES=0: fp32 C.
// ---------------------------------------------------------------------------
#define LDSg 40                 // bf16 row stride (80B): verified conflict-free
#define PSTG (128*LDSg*2)       // 10240 B per plane
#define SSTG (4*PSTG)           // 40960 B per stage (Ah, Al, Bh, Bl)
#define GDSM (2*SSTG)           // 81920 B dynamic smem

template<int PLANES>
__global__ __launch_bounds__(256, 1)
void gemm_planes(const __nv_bfloat16* __restrict__ Ah, const __nv_bfloat16* __restrict__ Al,
                 const __nv_bfloat16* __restrict__ Bh, const __nv_bfloat16* __restrict__ Bl,
                 float* __restrict__ C, __nv_bfloat16* __restrict__ Ch,
                 __nv_bfloat16* __restrict__ Cl, float scale) {
    extern __shared__ char dsm[];
    const uint32_t base = smem_u32(dsm);
    const int tid = threadIdx.x, lane = tid & 31, warp = tid >> 5;
    const int wm = (warp & 1) * 64;
    const int wn = (warp >> 1) * 32;
    const int bm = blockIdx.y * 128;
    const int bn = blockIdx.x * 128;

    const __nv_bfloat16* gp[4] = {
        Ah + (size_t)bm * DM, Al + (size_t)bm * DM,
        Bh + (size_t)bn * DM, Bl + (size_t)bn * DM };

    float acc[4][4][4];
#pragma unroll
    for (int i = 0; i < 4; i++)
#pragma unroll
        for (int j = 0; j < 4; j++)
#pragma unroll
            for (int v = 0; v < 4; v++) acc[i][j][v] = 0.f;

    // Stage load: 4 planes x 128 rows x 4 x 16B chunks = 2048 chunks, 8/thread.
#define G_LOAD(s, k0)                                                           \
    {                                                                           \
        uint32_t sb = base + (uint32_t)(s) * SSTG;                              \
        _Pragma("unroll")                                                       \
        for (int i = 0; i < 8; i++) {                                           \
            int id = tid + i * 256;                                             \
            int pl = id >> 9, cid = id & 511;                                   \
            int r = cid >> 2, ch = cid & 3;                                     \
            cpa16(sb + pl * PSTG + r * (LDSg * 2) + ch * 16,                    \
                  gp[pl] + (size_t)r * DM + (k0) + ch * 8);                     \
        }                                                                       \
        cpa_commit();                                                           \
    }

    G_LOAD(0, 0);

    for (int kt = 0; kt < DM / 32; kt++) {
        if (kt + 1 < DM / 32) { G_LOAD((kt + 1) & 1, (kt + 1) * 32); cpa_wait1(); }
        else                  { cpa_wait0(); }
        __syncthreads();

        const uint32_t sb = base + (uint32_t)(kt & 1) * SSTG;
        const uint32_t sAh = sb, sAl = sb + PSTG;
        const uint32_t sBh = sb + 2 * PSTG, sBl = sb + 3 * PSTG;

#pragma unroll
        for (int kk = 0; kk < 2; kk++) {
            uint32_t ah[4][4], al[4][4], bh[2][4], bl[2][4];
            const int acol = kk * 16 + (lane >> 4) * 8;
#pragma unroll
            for (int i = 0; i < 4; i++) {
                int arow = wm + i * 16 + (lane & 15);
                uint32_t off = (uint32_t)arow * (LDSg * 2) + acol * 2;
                ldm4(ah[i], sAh + off);
                ldm4(al[i], sAl + off);
            }
            const int bcol = kk * 16 + ((lane >> 3) & 1) * 8;
            const int brow_off = (lane & 7) + (lane >> 4) * 8;
#pragma unroll
            for (int j2 = 0; j2 < 2; j2++) {
                int brow = wn + j2 * 16 + brow_off;
                uint32_t off = (uint32_t)brow * (LDSg * 2) + bcol * 2;
                ldm4(bh[j2], sBh + off);
                ldm4(bl[j2], sBl + off);
            }
#pragma unroll
            for (int i = 0; i < 4; i++)
#pragma unroll
                for (int j = 0; j < 4; j++) {
                    const uint32_t* bhp = &bh[j >> 1][(j & 1) * 2];
                    const uint32_t* blp = &bl[j >> 1][(j & 1) * 2];
                    mma16816(acc[i][j], ah[i], bhp);
                    mma16816(acc[i][j], ah[i], blp);
                    mma16816(acc[i][j], al[i], bhp);
                }
        }
        __syncthreads();
    }

    const int g  = lane >> 2;
    const int t2 = (lane & 3) * 2;
#pragma unroll
    for (int i = 0; i < 4; i++)
#pragma unroll
        for (int j = 0; j < 4; j++) {
            int row = bm + wm + i * 16 + g;
            int col = bn + wn + j * 8 + t2;
            size_t i0 = (size_t)row * DM + col;
            size_t i1 = (size_t)(row + 8) * DM + col;
            if (PLANES) {
                float v0 = acc[i][j][0] * scale, v1 = acc[i][j][1] * scale;
                float v2 = acc[i][j][2] * scale, v3 = acc[i][j][3] * scale;
                *(uint32_t*)(Ch + i0) = bf2pack(v0, v1);
                *(uint32_t*)(Cl + i0) = bf2pack(bf16res(v0), bf16res(v1));
                *(uint32_t*)(Ch + i1) = bf2pack(v2, v3);
                *(uint32_t*)(Cl + i1) = bf2pack(bf16res(v2), bf16res(v3));
            } else {
                *(float2*)(C + i0) = make_float2(acc[i][j][0], acc[i][j][1]);
                *(float2*)(C + i1) = make_float2(acc[i][j][2], acc[i][j][3]);
            }
        }
#undef G_LOAD
}

// ---------------------------------------------------------------------------
// Tensor-core flash attention (split-bf16, fp32 accum); epilogue writes
// bf16 hi/lo planes for the final projection.
// ---------------------------------------------------------------------------
#define LDA 72

__global__ __launch_bounds__(128) void attn_mma(
    const __nv_bfloat16* __restrict__ Qh, const __nv_bfloat16* __restrict__ Ql,
    const __nv_bfloat16* __restrict__ Kh, const __nv_bfloat16* __restrict__ Kl,
    const __nv_bfloat16* __restrict__ Vh, const __nv_bfloat16* __restrict__ Vl,
    const uint32_t* __restrict__ Mb,
    __nv_bfloat16* __restrict__ Oh, __nv_bfloat16* __restrict__ Ol) {
    __shared__ __nv_bfloat16 sKh[64][LDA], sKl[64][LDA];
    __shared__ __nv_bfloat16 sVh[64][LDA], sVl[64][LDA];

    const int b = blockIdx.z, h = blockIdx.y;
    const int q0 = blockIdx.x * 64;
    const int tid = threadIdx.x, lane = tid & 31, warp = tid >> 5;
    const int g = lane >> 2, t2 = (lane & 3) * 2;

    for (int idx = tid; idx < 512; idx += 128) {
        int r = idx >> 3, c = (idx & 7) * 8;
        size_t go = (size_t)(b * SEQ + q0 + r) * DM + h * HD + c;
        *(uint4*)&sKh[r][c] = *(const uint4*)(Qh + go);
        *(uint4*)&sKl[r][c] = *(const uint4*)(Ql + go);
    }
    __syncthreads();
    uint32_t qh[4][4], ql[4][4];
    {
        int arow = warp * 16 + (lane & 15);
#pragma unroll
        for (int kk = 0; kk < 4; kk++) {
            int acol = kk * 16 + (lane >> 4) * 8;
            ldm4(qh[kk], smem_u32(&sKh[arow][acol]));
            ldm4(ql[kk], smem_u32(&sKl[arow][acol]));
        }
    }
    __syncthreads();

    float oa[8][4];
#pragma unroll
    for (int j = 0; j < 8; j++)
#pragma unroll
        for (int v = 0; v < 4; v++) oa[j][v] = 0.f;
    float mx0 = -INFINITY, mx1 = -INFINITY, l0 = 0.f, l1 = 0.f;

    const uint32_t* mr0 = Mb + (size_t)(b * SEQ + q0 + warp * 16 + g) * (SEQ / 32);
    const uint32_t* mr1 = mr0 + 8 * (SEQ / 32);

    for (int kt = 0; kt < SEQ / 64; kt++) {
        for (int idx = tid; idx < 512; idx += 128) {
            int r = idx >> 3, c = (idx & 7) * 8;
            size_t go = (size_t)(b * SEQ + kt * 64 + r) * DM + h * HD + c;
            *(uint4*)&sKh[r][c] = *(const uint4*)(Kh + go);
            *(uint4*)&sKl[r][c] = *(const uint4*)(Kl + go);
            *(uint4*)&sVh[r][c] = *(const uint4*)(Vh + go);
            *(uint4*)&sVl[r][c] = *(const uint4*)(Vl + go);
        }
        __syncthreads();

        float s[8][4];
#pragma unroll
        for (int j = 0; j < 8; j++)
#pragma unroll
            for (int v = 0; v < 4; v++) s[j][v] = 0.f;
#pragma unroll
        for (int kk = 0; kk < 4; kk++) {
            uint32_t bh[4][4], bl[4][4];
            const int bro = (lane & 7) + (lane >> 4) * 8;
            const int bco = kk * 16 + ((lane >> 3) & 1) * 8;
#pragma unroll
            for (int j2 = 0; j2 < 4; j2++) {
                ldm4(bh[j2], smem_u32(&sKh[j2 * 16 + bro][bco]));
                ldm4(bl[j2], smem_u32(&sKl[j2 * 16 + bro][bco]));
            }
#pragma unroll
            for (int j = 0; j < 8; j++) {
                const uint32_t* bhp = &bh[j >> 1][(j & 1) * 2];
                const uint32_t* blp = &bl[j >> 1][(j & 1) * 2];
                mma16816(s[j], qh[kk], bhp);
                mma16816(s[j], qh[kk], blp);
                mma16816(s[j], ql[kk], bhp);
            }
        }

        uint32_t w0a = mr0[kt * 2], w0b = mr0[kt * 2 + 1];
        uint32_t w1a = mr1[kt * 2], w1b = mr1[kt * 2 + 1];
#pragma unroll
        for (int j = 0; j < 8; j++) {
            uint32_t wr0 = (j < 4) ? w0a : w0b;
            uint32_t wr1 = (j < 4) ? w1a : w1b;
            int sh = (j * 8 + t2) & 31;
            if (!((wr0 >> sh) & 1u))       s[j][0] = -1e20f;
            if (!((wr0 >> (sh + 1)) & 1u)) s[j][1] = -1e20f;
            if (!((wr1 >> sh) & 1u))       s[j][2] = -1e20f;
            if (!((wr1 >> (sh + 1)) & 1u)) s[j][3] = -1e20f;
        }

        float tm0 = s[0][0], tm1 = s[0][2];
#pragma unroll
        for (int j = 0; j < 8; j++) {
            tm0 = fmaxf(tm0, fmaxf(s[j][0], s[j][1]));
            tm1 = fmaxf(tm1, fmaxf(s[j][2], s[j][3]));
        }
        tm0 = fmaxf(tm0, __shfl_xor_sync(0xffffffffu, tm0, 1));
        tm0 = fmaxf(tm0, __shfl_xor_sync(0xffffffffu, tm0, 2));
        tm1 = fmaxf(tm1, __shfl_xor_sync(0xffffffffu, tm1, 1));
        tm1 = fmaxf(tm1, __shfl_xor_sync(0xffffffffu, tm1, 2));
        float nm0 = fmaxf(mx0, tm0), nm1 = fmaxf(mx1, tm1);
        float cr0 = __expf(mx0 - nm0), cr1 = __expf(mx1 - nm1);
        mx0 = nm0; mx1 = nm1;

        float ps0 = 0.f, ps1 = 0.f;
#pragma unroll
        for (int j = 0; j < 8; j++) {
            s[j][0] = __expf(s[j][0] - nm0); ps0 += s[j][0];
            s[j][1] = __expf(s[j][1] - nm0); ps0 += s[j][1];
            s[j][2] = __expf(s[j][2] - nm1); ps1 += s[j][2];
            s[j][3] = __expf(s[j][3] - nm1); ps1 += s[j][3];
        }
        ps0 += __shfl_xor_sync(0xffffffffu, ps0, 1);
        ps0 += __shfl_xor_sync(0xffffffffu, ps0, 2);
        ps1 += __shfl_xor_sync(0xffffffffu, ps1, 1);
        ps1 += __shfl_xor_sync(0xffffffffu, ps1, 2);
        l0 = l0 * cr0 + ps0;
        l1 = l1 * cr1 + ps1;
#pragma unroll
        for (int j = 0; j < 8; j++) {
            oa[j][0] *= cr0; oa[j][1] *= cr0;
            oa[j][2] *= cr1; oa[j][3] *= cr1;
        }

        uint32_t ph[4][4], pl[4][4];
#pragma unroll
        for (int s4 = 0; s4 < 4; s4++) {
            int ta = 2 * s4, tb = ta + 1;
            ph[s4][0] = bf2pack(s[ta][0], s[ta][1]);
            ph[s4][1] = bf2pack(s[ta][2], s[ta][3]);
            ph[s4][2] = bf2pack(s[tb][0], s[tb][1]);
            ph[s4][3] = bf2pack(s[tb][2], s[tb][3]);
            pl[s4][0] = bf2pack(bf16res(s[ta][0]), bf16res(s[ta][1]));
            pl[s4][1] = bf2pack(bf16res(s[ta][2]), bf16res(s[ta][3]));
            pl[s4][2] = bf2pack(bf16res(s[tb][0]), bf16res(s[tb][1]));
            pl[s4][3] = bf2pack(bf16res(s[tb][2]), bf16res(s[tb][3]));
        }

#pragma unroll
        for (int s4 = 0; s4 < 4; s4++) {
            uint32_t vh[4][4], vl[4][4];
            const int vrow = s4 * 16 + ((lane >> 3) & 1) * 8 + (lane & 7);
#pragma unroll
            for (int n2 = 0; n2 < 4; n2++) {
                int vcol = n2 * 16 + (lane >> 4) * 8;
                ldm4t(vh[n2], smem_u32(&sVh[vrow][vcol]));
                ldm4t(vl[n2], smem_u32(&sVl[vrow][vcol]));
            }
#pragma unroll
            for (int j = 0; j < 8; j++) {
                const uint32_t* bhp = &vh[j >> 1][(j & 1) * 2];
                const uint32_t* blp = &vl[j >> 1][(j & 1) * 2];
                mma16816(oa[j], ph[s4], bhp);
                mma16816(oa[j], ph[s4], blp);
                mma16816(oa[j], pl[s4], bhp);
            }
        }
        __syncthreads();
    }

    float il0 = 1.f / l0, il1 = 1.f / l1;
    int row0 = b * SEQ + q0 + warp * 16 + g;
    size_t b0 = (size_t)row0 * DM + h * HD;
    size_t b1 = b0 + (size_t)8 * DM;
#pragma unroll
    for (int j = 0; j < 8; j++) {
        float v0 = oa[j][0] * il0, v1 = oa[j][1] * il0;
        float v2 = oa[j][2] * il1, v3 = oa[j][3] * il1;
        *(uint32_t*)(Oh + b0 + j * 8 + t2) = bf2pack(v0, v1);
        *(uint32_t*)(Ol + b0 + j * 8 + t2) = bf2pack(bf16res(v0), bf16res(v1));
        *(uint32_t*)(Oh + b1 + j * 8 + t2) = bf2pack(v2, v3);
        *(uint32_t*)(Ol + b1 + j * 8 + t2) = bf2pack(bf16res(v2), bf16res(v3));
    }
}

// ---------------------------------------------------------------------------
extern "C" void kernel_launch(void* const* d_in, const int* in_sizes, int n_in,
                              void* d_out, int out_size) {
    const float* query = (const float*)d_in[0];
    const float* key_t = (const float*)d_in[1];
    const float* value = (const float*)d_in[2];
    const int*   mask  = (const int*)d_in[3];
    const float* wq    = (const float*)d_in[4];
    const float* wk    = (const float*)d_in[5];
    const float* wv    = (const float*)d_in[6];
    const float* wo    = (const float*)d_in[7];
    float* out = (float*)d_out;

    __nv_bfloat16 *iQh, *iQl, *iKh, *iKl, *iVh, *iVl;
    __nv_bfloat16 *wqh, *wql, *wkh, *wkl, *wvh, *wvl, *woh, *wol;
    __nv_bfloat16 *Qh, *Ql, *Kh, *Kl, *Vh, *Vl, *Oh, *Ol;
    uint32_t* Mb;
    cudaGetSymbolAddress((void**)&iQh, g_iQh); cudaGetSymbolAddress((void**)&iQl, g_iQl);
    cudaGetSymbolAddress((void**)&iKh, g_iKh); cudaGetSymbolAddress((void**)&iKl, g_iKl);
    cudaGetSymbolAddress((void**)&iVh, g_iVh); cudaGetSymbolAddress((void**)&iVl, g_iVl);
    cudaGetSymbolAddress((void**)&wqh, g_wqh); cudaGetSymbolAddress((void**)&wql, g_wql);
    cudaGetSymbolAddress((void**)&wkh, g_wkh); cudaGetSymbolAddress((void**)&wkl, g_wkl);
    cudaGetSymbolAddress((void**)&wvh, g_wvh); cudaGetSymbolAddress((void**)&wvl, g_wvl);
    cudaGetSymbolAddress((void**)&woh, g_woh); cudaGetSymbolAddress((void**)&wol, g_wol);
    cudaGetSymbolAddress((void**)&Qh, g_Qh);   cudaGetSymbolAddress((void**)&Ql, g_Ql);
    cudaGetSymbolAddress((void**)&Kh, g_Kh);   cudaGetSymbolAddress((void**)&Kl, g_Kl);
    cudaGetSymbolAddress((void**)&Vh, g_Vh);   cudaGetSymbolAddress((void**)&Vl, g_Vl);
    cudaGetSymbolAddress((void**)&Oh, g_Oh);   cudaGetSymbolAddress((void**)&Ol, g_Ol);
    cudaGetSymbolAddress((void**)&Mb, g_Mb);

    static bool attr_set = false;
    if (!attr_set) {
        cudaFuncSetAttribute(gemm_planes<1>, cudaFuncAttributeMaxDynamicSharedMemorySize, GDSM);
        cudaFuncSetAttribute(gemm_planes<0>, cudaFuncAttributeMaxDynamicSharedMemorySize, GDSM);
        attr_set = true;
    }

    pack_mask<<<MWORDS * 32 / 256, 256>>>(mask, Mb);

    conv_split<<<NTOK * DM / 1024, 256>>>(query, iQh, iQl);
    conv_split<<<NTOK * DM / 1024, 256>>>(key_t, iKh, iKl);
    conv_split<<<NTOK * DM / 1024, 256>>>(value, iVh, iVl);
    conv_split<<<DM * DM / 1024, 256>>>(wq, wqh, wql);
    conv_split<<<DM * DM / 1024, 256>>>(wk, wkh, wkl);
    conv_split<<<DM * DM / 1024, 256>>>(wv, wvh, wvl);
    conv_split<<<DM * DM / 1024, 256>>>(wo, woh, wol);

    dim3 gg(DM / 128, NTOK / 128);   // (8, 32)
    gemm_planes<1><<<gg, 256, GDSM>>>(iQh, iQl, wqh, wql, nullptr, Qh, Ql, 0.125f);
    gemm_planes<1><<<gg, 256, GDSM>>>(iKh, iKl, wkh, wkl, nullptr, Kh, Kl, 1.0f);
    gemm_planes<1><<<gg, 256, GDSM>>>(iVh, iVl, wvh, wvl, nullptr, Vh, Vl, 1.0f);

    dim3 ga(SEQ / 64, NH, BATCH);    // (32, 16, 2)
    attn_mma<<<ga, 128>>>(Qh, Ql, Kh, Kl, Vh, Vl, Mb, Oh, Ol);

    gemm_planes<0><<<gg, 256, GDSM>>>(Oh, Ol, woh, wol, out, nullptr, nullptr, 1.0f);
}

// round 6
// speedup vs baseline: 4.2672x; 1.7467x over previous
#include <cuda_runtime.h>
#include <cuda_fp16.h>
#include <math.h>
#include <stdint.h>

#define DM   1024
#define HD   64
#define NH   16
#define BATCH 2
#define SEQ  2048
#define NTOK (BATCH*SEQ)
#define MWORDS (BATCH*SEQ*SEQ/32)

// ---------------------------------------------------------------------------
// Scratch (no allocations allowed).  fp16 planes; A-operands split (hi+lo),
// B-operands hi only (2-MMA split scheme).
// ---------------------------------------------------------------------------
__device__ __half g_iQh[NTOK*DM], g_iQl[NTOK*DM];
__device__ __half g_iKh[NTOK*DM], g_iKl[NTOK*DM];
__device__ __half g_iVh[NTOK*DM], g_iVl[NTOK*DM];
__device__ __half g_wqh[DM*DM], g_wkh[DM*DM], g_wvh[DM*DM], g_woh[DM*DM];
__device__ __half g_Qh[NTOK*DM], g_Ql[NTOK*DM];   // Q split (A of QK^T)
__device__ __half g_Kh[NTOK*DM];                  // K hi only (B of QK^T)
__device__ __half g_Vh[NTOK*DM];                  // V hi only (B of PV)
__device__ __half g_Oh[NTOK*DM], g_Ol[NTOK*DM];   // O split (A of final gemm)
__device__ uint32_t g_Mb[MWORDS];

// ---------------------------------------------------------------------------
// Helpers
// ---------------------------------------------------------------------------
__device__ __forceinline__ uint32_t smem_u32(const void* p) {
    uint32_t a;
    asm("{ .reg .u64 t; cvta.to.shared.u64 t, %1; cvt.u32.u64 %0, t; }" : "=r"(a) : "l"(p));
    return a;
}
__device__ __forceinline__ uint32_t h2pack(float lo, float hi) {
    __half2 t = __floats2half2_rn(lo, hi);
    return *reinterpret_cast<uint32_t*>(&t);
}
__device__ __forceinline__ float h16res(float x) {
    return x - __half2float(__float2half_rn(x));
}
__device__ __forceinline__ void ldm4(uint32_t* r, uint32_t addr) {
    asm volatile("ldmatrix.sync.aligned.m8n8.x4.shared.b16 {%0,%1,%2,%3}, [%4];"
                 : "=r"(r[0]), "=r"(r[1]), "=r"(r[2]), "=r"(r[3]) : "r"(addr));
}
__device__ __forceinline__ void ldm4t(uint32_t* r, uint32_t addr) {
    asm volatile("ldmatrix.sync.aligned.m8n8.x4.trans.shared.b16 {%0,%1,%2,%3}, [%4];"
                 : "=r"(r[0]), "=r"(r[1]), "=r"(r[2]), "=r"(r[3]) : "r"(addr));
}
__device__ __forceinline__ void mma16816(float* c, const uint32_t* a, const uint32_t* b) {
    asm volatile(
        "mma.sync.aligned.m16n8k16.row.col.f32.f16.f16.f32 "
        "{%0,%1,%2,%3}, {%4,%5,%6,%7}, {%8,%9}, {%0,%1,%2,%3};\n"
        : "+f"(c[0]), "+f"(c[1]), "+f"(c[2]), "+f"(c[3])
        : "r"(a[0]), "r"(a[1]), "r"(a[2]), "r"(a[3]), "r"(b[0]), "r"(b[1]));
}
__device__ __forceinline__ void cpa16(uint32_t dst, const void* src) {
    asm volatile("cp.async.cg.shared.global [%0], [%1], 16;" :: "r"(dst), "l"(src) : "memory");
}
__device__ __forceinline__ void cpa_commit() { asm volatile("cp.async.commit_group;" ::: "memory"); }
__device__ __forceinline__ void cpa_wait1()  { asm volatile("cp.async.wait_group 1;" ::: "memory"); }
__device__ __forceinline__ void cpa_wait0()  { asm volatile("cp.async.wait_group 0;" ::: "memory"); }

// ---------------------------------------------------------------------------
// Mask -> bitmask
// ---------------------------------------------------------------------------
__global__ __launch_bounds__(256) void pack_mask(const int* __restrict__ mask,
                                                 uint32_t* __restrict__ bits) {
    int t = blockIdx.x * blockDim.x + threadIdx.x;
    unsigned bal = __ballot_sync(0xffffffffu, mask[t] != 0);
    if ((t & 31) == 0) bits[t >> 5] = bal;
}

// ---------------------------------------------------------------------------
// fp32 -> fp16 conversions
// ---------------------------------------------------------------------------
__global__ __launch_bounds__(256) void conv_split2(const float* __restrict__ x,
                                                   __half* __restrict__ xh,
                                                   __half* __restrict__ xl) {
    int t = blockIdx.x * blockDim.x + threadIdx.x;
    float4 v = ((const float4*)x)[t];
    ((uint2*)xh)[t] = make_uint2(h2pack(v.x, v.y), h2pack(v.z, v.w));
    ((uint2*)xl)[t] = make_uint2(h2pack(h16res(v.x), h16res(v.y)),
                                 h2pack(h16res(v.z), h16res(v.w)));
}
__global__ __launch_bounds__(256) void conv_hi(const float* __restrict__ x,
                                               __half* __restrict__ xh) {
    int t = blockIdx.x * blockDim.x + threadIdx.x;
    float4 v = ((const float4*)x)[t];
    ((uint2*)xh)[t] = make_uint2(h2pack(v.x, v.y), h2pack(v.z, v.w));
}

// ---------------------------------------------------------------------------
// 2-MMA split-fp16 GEMM:  C[m][n] = sum_k A[m][k]*B[n][k]
// A split (Ah+Al), B hi only.  Tile 128x128, BK=32, cp.async double-buffered,
// 8 warps (2m x 4n).  MODE 2: write split fp16 planes (scaled).
// MODE 1: hi plane only (scaled).  MODE 0: fp32 C.
// ---------------------------------------------------------------------------
#define LDSg 40                 // fp16 row stride (80B), conflict-free ldmatrix
#define PSTG (128*LDSg*2)       // 10240 B per plane
#define SSTG (3*PSTG)           // 30720 B per stage (Ah, Al, Bh)
#define GDSM (2*SSTG)           // 61440 B dynamic smem

template<int MODE>
__global__ __launch_bounds__(256, 2)
void gemm_fp16(const __half* __restrict__ Ah, const __half* __restrict__ Al,
               const __half* __restrict__ Bh,
               float* __restrict__ C, __half* __restrict__ Ch,
               __half* __restrict__ Cl, float scale) {
    extern __shared__ char dsm[];
    const uint32_t base = smem_u32(dsm);
    const int tid = threadIdx.x, lane = tid & 31, warp = tid >> 5;
    const int wm = (warp & 1) * 64;
    const int wn = (warp >> 1) * 32;
    const int bm = blockIdx.y * 128;
    const int bn = blockIdx.x * 128;

    const __half* gp[3] = { Ah + (size_t)bm * DM, Al + (size_t)bm * DM,
                            Bh + (size_t)bn * DM };

    float acc[4][4][4];
#pragma unroll
    for (int i = 0; i < 4; i++)
#pragma unroll
        for (int j = 0; j < 4; j++)
#pragma unroll
            for (int v = 0; v < 4; v++) acc[i][j][v] = 0.f;

    // Stage load: 3 planes x 128 rows x 4 x 16B chunks = 1536 chunks, 6/thread.
#define G_LOAD(s, k0)                                                           \
    {                                                                           \
        uint32_t sb = base + (uint32_t)(s) * SSTG;                              \
        _Pragma("unroll")                                                       \
        for (int i = 0; i < 6; i++) {                                           \
            int id = tid + i * 256;                                             \
            int pl = id >> 9, cid = id & 511;                                   \
            int r = cid >> 2, ch = cid & 3;                                     \
            cpa16(sb + pl * PSTG + r * (LDSg * 2) + ch * 16,                    \
                  gp[pl] + (size_t)r * DM + (k0) + ch * 8);                     \
        }                                                                       \
        cpa_commit();                                                           \
    }

    G_LOAD(0, 0);

    for (int kt = 0; kt < DM / 32; kt++) {
        if (kt + 1 < DM / 32) { G_LOAD((kt + 1) & 1, (kt + 1) * 32); cpa_wait1(); }
        else                  { cpa_wait0(); }
        __syncthreads();

        const uint32_t sb = base + (uint32_t)(kt & 1) * SSTG;
        const uint32_t sAh = sb, sAl = sb + PSTG, sBh = sb + 2 * PSTG;

#pragma unroll
        for (int kk = 0; kk < 2; kk++) {
            uint32_t ah[4][4], al[4][4], bh[2][4];
            const int acol = kk * 16 + (lane >> 4) * 8;
#pragma unroll
            for (int i = 0; i < 4; i++) {
                int arow = wm + i * 16 + (lane & 15);
                uint32_t off = (uint32_t)arow * (LDSg * 2) + acol * 2;
                ldm4(ah[i], sAh + off);
                ldm4(al[i], sAl + off);
            }
            const int bcol = kk * 16 + ((lane >> 3) & 1) * 8;
            const int brow_off = (lane & 7) + (lane >> 4) * 8;
#pragma unroll
            for (int j2 = 0; j2 < 2; j2++) {
                int brow = wn + j2 * 16 + brow_off;
                ldm4(bh[j2], sBh + (uint32_t)brow * (LDSg * 2) + bcol * 2);
            }
#pragma unroll
            for (int i = 0; i < 4; i++)
#pragma unroll
                for (int j = 0; j < 4; j++) {
                    const uint32_t* bhp = &bh[j >> 1][(j & 1) * 2];
                    mma16816(acc[i][j], ah[i], bhp);
                    mma16816(acc[i][j], al[i], bhp);
                }
        }
        __syncthreads();
    }

    const int g  = lane >> 2;
    const int t2 = (lane & 3) * 2;
#pragma unroll
    for (int i = 0; i < 4; i++)
#pragma unroll
        for (int j = 0; j < 4; j++) {
            int row = bm + wm + i * 16 + g;
            int col = bn + wn + j * 8 + t2;
            size_t i0 = (size_t)row * DM + col;
            size_t i1 = (size_t)(row + 8) * DM + col;
            float v0 = acc[i][j][0] * scale, v1 = acc[i][j][1] * scale;
            float v2 = acc[i][j][2] * scale, v3 = acc[i][j][3] * scale;
            if (MODE == 0) {
                *(float2*)(C + i0) = make_float2(v0, v1);
                *(float2*)(C + i1) = make_float2(v2, v3);
            } else {
                *(uint32_t*)(Ch + i0) = h2pack(v0, v1);
                *(uint32_t*)(Ch + i1) = h2pack(v2, v3);
                if (MODE == 2) {
                    *(uint32_t*)(Cl + i0) = h2pack(h16res(v0), h16res(v1));
                    *(uint32_t*)(Cl + i1) = h2pack(h16res(v2), h16res(v3));
                }
            }
        }
#undef G_LOAD
}

// ---------------------------------------------------------------------------
// 2-MMA split-fp16 flash attention.  64 q-rows x one head per CTA, 4 warps.
// K/V hi-planes cp.async double-buffered; Q split (pre-scaled by 1/8).
// ---------------------------------------------------------------------------
#define LDA 72                   // fp16 row stride (144B), conflict-free
#define APLN (64*LDA*2)          // 9216 B per plane
#define ASTG (2*APLN)            // 18432 B per stage (Kh, Vh)
#define ADSM (2*ASTG)            // 36864 B dynamic smem

__global__ __launch_bounds__(128, 2) void attn_fp16(
    const __half* __restrict__ Qh, const __half* __restrict__ Ql,
    const __half* __restrict__ Kh, const __half* __restrict__ Vh,
    const uint32_t* __restrict__ Mb,
    __half* __restrict__ Oh, __half* __restrict__ Ol) {
    extern __shared__ char dsm[];
    const uint32_t base = smem_u32(dsm);

    const int b = blockIdx.z, h = blockIdx.y;
    const int q0 = blockIdx.x * 64;
    const int tid = threadIdx.x, lane = tid & 31, warp = tid >> 5;
    const int g = lane >> 2, t2 = (lane & 3) * 2;

    // Prologue: stage Q planes in stage-0 buffers, read A fragments.
    {
        __half* sQh = (__half*)(dsm);
        __half* sQl = (__half*)(dsm + APLN);
        for (int idx = tid; idx < 512; idx += 128) {
            int r = idx >> 3, c = (idx & 7) * 8;
            size_t go = (size_t)(b * SEQ + q0 + r) * DM + h * HD + c;
            *(uint4*)(sQh + r * LDA + c) = *(const uint4*)(Qh + go);
            *(uint4*)(sQl + r * LDA + c) = *(const uint4*)(Ql + go);
        }
    }
    __syncthreads();
    uint32_t qh[4][4], ql[4][4];
    {
        int arow = warp * 16 + (lane & 15);
#pragma unroll
        for (int kk = 0; kk < 4; kk++) {
            int acol = kk * 16 + (lane >> 4) * 8;
            uint32_t off = (uint32_t)arow * (LDA * 2) + acol * 2;
            ldm4(qh[kk], base + off);
            ldm4(ql[kk], base + APLN + off);
        }
    }
    __syncthreads();

    // Stage load: Kh + Vh, 2 planes x 64 rows x 8 x 16B = 1024 chunks, 8/thread.
#define A_LOAD(s, kt)                                                           \
    {                                                                           \
        uint32_t sb = base + (uint32_t)(s) * ASTG;                              \
        const __half* gsrc[2] = { Kh, Vh };                                     \
        _Pragma("unroll")                                                       \
        for (int i = 0; i < 8; i++) {                                           \
            int id = tid + i * 128;                                             \
            int ar = id >> 9, cid = id & 511;                                   \
            int r = cid >> 3, ch = cid & 7;                                     \
            cpa16(sb + ar * APLN + r * (LDA * 2) + ch * 16,                     \
                  gsrc[ar] + (size_t)(b * SEQ + (kt) * 64 + r) * DM + h * HD + ch * 8); \
        }                                                                       \
        cpa_commit();                                                           \
    }

    float oa[8][4];
#pragma unroll
    for (int j = 0; j < 8; j++)
#pragma unroll
        for (int v = 0; v < 4; v++) oa[j][v] = 0.f;
    float mx0 = -INFINITY, mx1 = -INFINITY, l0 = 0.f, l1 = 0.f;

    const uint32_t* mr0 = Mb + (size_t)(b * SEQ + q0 + warp * 16 + g) * (SEQ / 32);
    const uint32_t* mr1 = mr0 + 8 * (SEQ / 32);

    A_LOAD(0, 0);

    for (int kt = 0; kt < SEQ / 64; kt++) {
        if (kt + 1 < SEQ / 64) { A_LOAD((kt + 1) & 1, kt + 1); cpa_wait1(); }
        else                   { cpa_wait0(); }
        __syncthreads();

        const uint32_t sK = base + (uint32_t)(kt & 1) * ASTG;
        const uint32_t sV = sK + APLN;

        // S = Q K^T  (2-MMA split: (qh+ql)*kh)
        float s[8][4];
#pragma unroll
        for (int j = 0; j < 8; j++)
#pragma unroll
            for (int v = 0; v < 4; v++) s[j][v] = 0.f;
#pragma unroll
        for (int kk = 0; kk < 4; kk++) {
            uint32_t bh[4][4];
            const int bro = (lane & 7) + (lane >> 4) * 8;
            const int bco = kk * 16 + ((lane >> 3) & 1) * 8;
#pragma unroll
            for (int j2 = 0; j2 < 4; j2++)
                ldm4(bh[j2], sK + (uint32_t)(j2 * 16 + bro) * (LDA * 2) + bco * 2);
#pragma unroll
            for (int j = 0; j < 8; j++) {
                const uint32_t* bhp = &bh[j >> 1][(j & 1) * 2];
                mma16816(s[j], qh[kk], bhp);
                mma16816(s[j], ql[kk], bhp);
            }
        }

        // Mask
        uint32_t w0a = mr0[kt * 2], w0b = mr0[kt * 2 + 1];
        uint32_t w1a = mr1[kt * 2], w1b = mr1[kt * 2 + 1];
#pragma unroll
        for (int j = 0; j < 8; j++) {
            uint32_t wr0 = (j < 4) ? w0a : w0b;
            uint32_t wr1 = (j < 4) ? w1a : w1b;
            int sh = (j * 8 + t2) & 31;
            if (!((wr0 >> sh) & 1u))       s[j][0] = -1e20f;
            if (!((wr0 >> (sh + 1)) & 1u)) s[j][1] = -1e20f;
            if (!((wr1 >> sh) & 1u))       s[j][2] = -1e20f;
            if (!((wr1 >> (sh + 1)) & 1u)) s[j][3] = -1e20f;
        }

        // Online softmax
        float tm0 = s[0][0], tm1 = s[0][2];
#pragma unroll
        for (int j = 0; j < 8; j++) {
            tm0 = fmaxf(tm0, fmaxf(s[j][0], s[j][1]));
            tm1 = fmaxf(tm1, fmaxf(s[j][2], s[j][3]));
        }
        tm0 = fmaxf(tm0, __shfl_xor_sync(0xffffffffu, tm0, 1));
        tm0 = fmaxf(tm0, __shfl_xor_sync(0xffffffffu, tm0, 2));
        tm1 = fmaxf(tm1, __shfl_xor_sync(0xffffffffu, tm1, 1));
        tm1 = fmaxf(tm1, __shfl_xor_sync(0xffffffffu, tm1, 2));
        float nm0 = fmaxf(mx0, tm0), nm1 = fmaxf(mx1, tm1);
        float cr0 = __expf(mx0 - nm0), cr1 = __expf(mx1 - nm1);
        mx0 = nm0; mx1 = nm1;

        float ps0 = 0.f, ps1 = 0.f;
#pragma unroll
        for (int j = 0; j < 8; j++) {
            s[j][0] = __expf(s[j][0] - nm0); ps0 += s[j][0];
            s[j][1] = __expf(s[j][1] - nm0); ps0 += s[j][1];
            s[j][2] = __expf(s[j][2] - nm1); ps1 += s[j][2];
            s[j][3] = __expf(s[j][3] - nm1); ps1 += s[j][3];
        }
        ps0 += __shfl_xor_sync(0xffffffffu, ps0, 1);
        ps0 += __shfl_xor_sync(0xffffffffu, ps0, 2);
        ps1 += __shfl_xor_sync(0xffffffffu, ps1, 1);
        ps1 += __shfl_xor_sync(0xffffffffu, ps1, 2);
        l0 = l0 * cr0 + ps0;
        l1 = l1 * cr1 + ps1;
#pragma unroll
        for (int j = 0; j < 8; j++) {
            oa[j][0] *= cr0; oa[j][1] *= cr0;
            oa[j][2] *= cr1; oa[j][3] *= cr1;
        }

        // P -> fp16 split A-fragments
        uint32_t ph[4][4], pl[4][4];
#pragma unroll
        for (int s4 = 0; s4 < 4; s4++) {
            int ta = 2 * s4, tb = ta + 1;
            ph[s4][0] = h2pack(s[ta][0], s[ta][1]);
            ph[s4][1] = h2pack(s[ta][2], s[ta][3]);
            ph[s4][2] = h2pack(s[tb][0], s[tb][1]);
            ph[s4][3] = h2pack(s[tb][2], s[tb][3]);
            pl[s4][0] = h2pack(h16res(s[ta][0]), h16res(s[ta][1]));
            pl[s4][1] = h2pack(h16res(s[ta][2]), h16res(s[ta][3]));
            pl[s4][2] = h2pack(h16res(s[tb][0]), h16res(s[tb][1]));
            pl[s4][3] = h2pack(h16res(s[tb][2]), h16res(s[tb][3]));
        }

        // O += P V  (2-MMA split: (ph+pl)*vh)
#pragma unroll
        for (int s4 = 0; s4 < 4; s4++) {
            uint32_t vh[4][4];
            const int vrow = s4 * 16 + ((lane >> 3) & 1) * 8 + (lane & 7);
#pragma unroll
            for (int n2 = 0; n2 < 4; n2++) {
                int vcol = n2 * 16 + (lane >> 4) * 8;
                ldm4t(vh[n2], sV + (uint32_t)vrow * (LDA * 2) + vcol * 2);
            }
#pragma unroll
            for (int j = 0; j < 8; j++) {
                const uint32_t* bhp = &vh[j >> 1][(j & 1) * 2];
                mma16816(oa[j], ph[s4], bhp);
                mma16816(oa[j], pl[s4], bhp);
            }
        }
        __syncthreads();
    }

    float il0 = 1.f / l0, il1 = 1.f / l1;
    int row0 = b * SEQ + q0 + warp * 16 + g;
    size_t b0 = (size_t)row0 * DM + h * HD;
    size_t b1 = b0 + (size_t)8 * DM;
#pragma unroll
    for (int j = 0; j < 8; j++) {
        float v0 = oa[j][0] * il0, v1 = oa[j][1] * il0;
        float v2 = oa[j][2] * il1, v3 = oa[j][3] * il1;
        *(uint32_t*)(Oh + b0 + j * 8 + t2) = h2pack(v0, v1);
        *(uint32_t*)(Ol + b0 + j * 8 + t2) = h2pack(h16res(v0), h16res(v1));
        *(uint32_t*)(Oh + b1 + j * 8 + t2) = h2pack(v2, v3);
        *(uint32_t*)(Ol + b1 + j * 8 + t2) = h2pack(h16res(v2), h16res(v3));
    }
#undef A_LOAD
}

// ---------------------------------------------------------------------------
extern "C" void kernel_launch(void* const* d_in, const int* in_sizes, int n_in,
                              void* d_out, int out_size) {
    const float* query = (const float*)d_in[0];
    const float* key_t = (const float*)d_in[1];
    const float* value = (const float*)d_in[2];
    const int*   mask  = (const int*)d_in[3];
    const float* wq    = (const float*)d_in[4];
    const float* wk    = (const float*)d_in[5];
    const float* wv    = (const float*)d_in[6];
    const float* wo    = (const float*)d_in[7];
    float* out = (float*)d_out;

    __half *iQh, *iQl, *iKh, *iKl, *iVh, *iVl;
    __half *wqh, *wkh, *wvh, *woh;
    __half *Qh, *Ql, *Kh, *Vh, *Oh, *Ol;
    uint32_t* Mb;
    cudaGetSymbolAddress((void**)&iQh, g_iQh); cudaGetSymbolAddress((void**)&iQl, g_iQl);
    cudaGetSymbolAddress((void**)&iKh, g_iKh); cudaGetSymbolAddress((void**)&iKl, g_iKl);
    cudaGetSymbolAddress((void**)&iVh, g_iVh); cudaGetSymbolAddress((void**)&iVl, g_iVl);
    cudaGetSymbolAddress((void**)&wqh, g_wqh); cudaGetSymbolAddress((void**)&wkh, g_wkh);
    cudaGetSymbolAddress((void**)&wvh, g_wvh); cudaGetSymbolAddress((void**)&woh, g_woh);
    cudaGetSymbolAddress((void**)&Qh, g_Qh);   cudaGetSymbolAddress((void**)&Ql, g_Ql);
    cudaGetSymbolAddress((void**)&Kh, g_Kh);   cudaGetSymbolAddress((void**)&Vh, g_Vh);
    cudaGetSymbolAddress((void**)&Oh, g_Oh);   cudaGetSymbolAddress((void**)&Ol, g_Ol);
    cudaGetSymbolAddress((void**)&Mb, g_Mb);

    static bool attr_set = false;
    if (!attr_set) {
        cudaFuncSetAttribute(gemm_fp16<2>, cudaFuncAttributeMaxDynamicSharedMemorySize, GDSM);
        cudaFuncSetAttribute(gemm_fp16<1>, cudaFuncAttributeMaxDynamicSharedMemorySize, GDSM);
        cudaFuncSetAttribute(gemm_fp16<0>, cudaFuncAttributeMaxDynamicSharedMemorySize, GDSM);
        cudaFuncSetAttribute(attn_fp16,    cudaFuncAttributeMaxDynamicSharedMemorySize, ADSM);
        attr_set = true;
    }

    pack_mask<<<MWORDS * 32 / 256, 256>>>(mask, Mb);

    conv_split2<<<NTOK * DM / 1024, 256>>>(query, iQh, iQl);
    conv_split2<<<NTOK * DM / 1024, 256>>>(key_t, iKh, iKl);
    conv_split2<<<NTOK * DM / 1024, 256>>>(value, iVh, iVl);
    conv_hi<<<DM * DM / 1024, 256>>>(wq, wqh);
    conv_hi<<<DM * DM / 1024, 256>>>(wk, wkh);
    conv_hi<<<DM * DM / 1024, 256>>>(wv, wvh);
    conv_hi<<<DM * DM / 1024, 256>>>(wo, woh);

    dim3 gg(DM / 128, NTOK / 128);   // (8, 32)
    gemm_fp16<2><<<gg, 256, GDSM>>>(iQh, iQl, wqh, nullptr, Qh, Ql, 0.125f);
    gemm_fp16<1><<<gg, 256, GDSM>>>(iKh, iKl, wkh, nullptr, Kh, nullptr, 1.0f);
    gemm_fp16<1><<<gg, 256, GDSM>>>(iVh, iVl, wvh, nullptr, Vh, nullptr, 1.0f);

    dim3 ga(SEQ / 64, NH, BATCH);    // (32, 16, 2)
    attn_fp16<<<ga, 128, ADSM>>>(Qh, Ql, Kh, Vh, Mb, Oh, Ol);

    gemm_fp16<0><<<gg, 256, GDSM>>>(Oh, Ol, woh, out, nullptr, nullptr, 1.0f);
}

// round 7
// speedup vs baseline: 6.1846x; 1.4493x over previous
#include <cuda_runtime.h>
#include <cuda_fp16.h>
#include <math.h>
#include <stdint.h>

#define DM   1024
#define HD   64
#define NH   16
#define BATCH 2
#define SEQ  2048
#define NTOK (BATCH*SEQ)
#define MWORDS (BATCH*SEQ*SEQ/32)

// ---------------------------------------------------------------------------
// Scratch (no allocations allowed).  Pure fp16 pipeline (1 MMA per product).
// ---------------------------------------------------------------------------
__device__ __half g_iQ[NTOK*DM], g_iK[NTOK*DM], g_iV[NTOK*DM];
__device__ __half g_wq[DM*DM], g_wk[DM*DM], g_wv[DM*DM], g_wo[DM*DM];
__device__ __half g_Q[NTOK*DM], g_K[NTOK*DM], g_V[NTOK*DM];
__device__ __half g_O[NTOK*DM];
__device__ uint32_t g_Mb[MWORDS];

// ---------------------------------------------------------------------------
// Helpers
// ---------------------------------------------------------------------------
__device__ __forceinline__ uint32_t smem_u32(const void* p) {
    uint32_t a;
    asm("{ .reg .u64 t; cvta.to.shared.u64 t, %1; cvt.u32.u64 %0, t; }" : "=r"(a) : "l"(p));
    return a;
}
__device__ __forceinline__ uint32_t h2pack(float lo, float hi) {
    __half2 t = __floats2half2_rn(lo, hi);
    return *reinterpret_cast<uint32_t*>(&t);
}
__device__ __forceinline__ void ldm4(uint32_t* r, uint32_t addr) {
    asm volatile("ldmatrix.sync.aligned.m8n8.x4.shared.b16 {%0,%1,%2,%3}, [%4];"
                 : "=r"(r[0]), "=r"(r[1]), "=r"(r[2]), "=r"(r[3]) : "r"(addr));
}
__device__ __forceinline__ void ldm4t(uint32_t* r, uint32_t addr) {
    asm volatile("ldmatrix.sync.aligned.m8n8.x4.trans.shared.b16 {%0,%1,%2,%3}, [%4];"
                 : "=r"(r[0]), "=r"(r[1]), "=r"(r[2]), "=r"(r[3]) : "r"(addr));
}
__device__ __forceinline__ void mma16816(float* c, const uint32_t* a, const uint32_t* b) {
    asm volatile(
        "mma.sync.aligned.m16n8k16.row.col.f32.f16.f16.f32 "
        "{%0,%1,%2,%3}, {%4,%5,%6,%7}, {%8,%9}, {%0,%1,%2,%3};\n"
        : "+f"(c[0]), "+f"(c[1]), "+f"(c[2]), "+f"(c[3])
        : "r"(a[0]), "r"(a[1]), "r"(a[2]), "r"(a[3]), "r"(b[0]), "r"(b[1]));
}
__device__ __forceinline__ void cpa16(uint32_t dst, const void* src) {
    asm volatile("cp.async.cg.shared.global [%0], [%1], 16;" :: "r"(dst), "l"(src) : "memory");
}
__device__ __forceinline__ void cpa_commit() { asm volatile("cp.async.commit_group;" ::: "memory"); }
__device__ __forceinline__ void cpa_wait1()  { asm volatile("cp.async.wait_group 1;" ::: "memory"); }
__device__ __forceinline__ void cpa_wait0()  { asm volatile("cp.async.wait_group 0;" ::: "memory"); }

// ---------------------------------------------------------------------------
// Mask -> bitmask
// ---------------------------------------------------------------------------
__global__ __launch_bounds__(256) void pack_mask(const int* __restrict__ mask,
                                                 uint32_t* __restrict__ bits) {
    int t = blockIdx.x * blockDim.x + threadIdx.x;
    unsigned bal = __ballot_sync(0xffffffffu, mask[t] != 0);
    if ((t & 31) == 0) bits[t >> 5] = bal;
}

// ---------------------------------------------------------------------------
// fp32 -> fp16
// ---------------------------------------------------------------------------
__global__ __launch_bounds__(256) void conv_hi(const float* __restrict__ x,
                                               __half* __restrict__ xh) {
    int t = blockIdx.x * blockDim.x + threadIdx.x;
    float4 v = ((const float4*)x)[t];
    ((uint2*)xh)[t] = make_uint2(h2pack(v.x, v.y), h2pack(v.z, v.w));
}

// ---------------------------------------------------------------------------
// fp16 GEMM:  C[m][n] = sum_k A[m][k]*B[n][k]   (both K-major, K=1024)
// Tile 128x128, BK=32, cp.async double-buffered, 8 warps (2m x 4n).
// MODE 1: fp16 C (scaled).  MODE 0: fp32 C.
// ---------------------------------------------------------------------------
#define LDSg 40                 // fp16 row stride (80B), conflict-free ldmatrix
#define PSTG (128*LDSg*2)       // 10240 B per plane
#define SSTG (2*PSTG)           // 20480 B per stage (A, B)
#define GDSM (2*SSTG)           // 40960 B dynamic smem

template<int MODE>
__global__ __launch_bounds__(256, 2)
void gemm_fp16(const __half* __restrict__ A, const __half* __restrict__ B,
               float* __restrict__ C, __half* __restrict__ Ch, float scale) {
    extern __shared__ char dsm[];
    const uint32_t base = smem_u32(dsm);
    const int tid = threadIdx.x, lane = tid & 31, warp = tid >> 5;
    const int wm = (warp & 1) * 64;
    const int wn = (warp >> 1) * 32;
    const int bm = blockIdx.y * 128;
    const int bn = blockIdx.x * 128;

    const __half* gp[2] = { A + (size_t)bm * DM, B + (size_t)bn * DM };

    float acc[4][4][4];
#pragma unroll
    for (int i = 0; i < 4; i++)
#pragma unroll
        for (int j = 0; j < 4; j++)
#pragma unroll
            for (int v = 0; v < 4; v++) acc[i][j][v] = 0.f;

    // Stage load: 2 planes x 128 rows x 4 x 16B chunks = 1024 chunks, 4/thread.
#define G_LOAD(s, k0)                                                           \
    {                                                                           \
        uint32_t sb = base + (uint32_t)(s) * SSTG;                              \
        _Pragma("unroll")                                                       \
        for (int i = 0; i < 4; i++) {                                           \
            int id = tid + i * 256;                                             \
            int pl = id >> 9, cid = id & 511;                                   \
            int r = cid >> 2, ch = cid & 3;                                     \
            cpa16(sb + pl * PSTG + r * (LDSg * 2) + ch * 16,                    \
                  gp[pl] + (size_t)r * DM + (k0) + ch * 8);                     \
        }                                                                       \
        cpa_commit();                                                           \
    }

    G_LOAD(0, 0);

    for (int kt = 0; kt < DM / 32; kt++) {
        if (kt + 1 < DM / 32) { G_LOAD((kt + 1) & 1, (kt + 1) * 32); cpa_wait1(); }
        else                  { cpa_wait0(); }
        __syncthreads();

        const uint32_t sb = base + (uint32_t)(kt & 1) * SSTG;
        const uint32_t sA = sb, sB = sb + PSTG;

#pragma unroll
        for (int kk = 0; kk < 2; kk++) {
            uint32_t ah[4][4], bh[2][4];
            const int acol = kk * 16 + (lane >> 4) * 8;
#pragma unroll
            for (int i = 0; i < 4; i++) {
                int arow = wm + i * 16 + (lane & 15);
                ldm4(ah[i], sA + (uint32_t)arow * (LDSg * 2) + acol * 2);
            }
            const int bcol = kk * 16 + ((lane >> 3) & 1) * 8;
            const int brow_off = (lane & 7) + (lane >> 4) * 8;
#pragma unroll
            for (int j2 = 0; j2 < 2; j2++) {
                int brow = wn + j2 * 16 + brow_off;
                ldm4(bh[j2], sB + (uint32_t)brow * (LDSg * 2) + bcol * 2);
            }
#pragma unroll
            for (int i = 0; i < 4; i++)
#pragma unroll
                for (int j = 0; j < 4; j++)
                    mma16816(acc[i][j], ah[i], &bh[j >> 1][(j & 1) * 2]);
        }
        __syncthreads();
    }

    const int g  = lane >> 2;
    const int t2 = (lane & 3) * 2;
#pragma unroll
    for (int i = 0; i < 4; i++)
#pragma unroll
        for (int j = 0; j < 4; j++) {
            int row = bm + wm + i * 16 + g;
            int col = bn + wn + j * 8 + t2;
            size_t i0 = (size_t)row * DM + col;
            size_t i1 = (size_t)(row + 8) * DM + col;
            float v0 = acc[i][j][0] * scale, v1 = acc[i][j][1] * scale;
            float v2 = acc[i][j][2] * scale, v3 = acc[i][j][3] * scale;
            if (MODE == 0) {
                *(float2*)(C + i0) = make_float2(v0, v1);
                *(float2*)(C + i1) = make_float2(v2, v3);
            } else {
                *(uint32_t*)(Ch + i0) = h2pack(v0, v1);
                *(uint32_t*)(Ch + i1) = h2pack(v2, v3);
            }
        }
#undef G_LOAD
}

// ---------------------------------------------------------------------------
// fp16 flash attention.  64 q-rows x one head per CTA, 4 warps.
// K/V cp.async double-buffered; Q pre-scaled by 1/8.
// ---------------------------------------------------------------------------
#define LDA 72                   // fp16 row stride (144B), conflict-free
#define APLN (64*LDA*2)          // 9216 B per plane
#define ASTG (2*APLN)            // 18432 B per stage (K, V)
#define ADSM (2*ASTG)            // 36864 B dynamic smem

__global__ __launch_bounds__(128, 3) void attn_fp16(
    const __half* __restrict__ Q, const __half* __restrict__ K,
    const __half* __restrict__ V, const uint32_t* __restrict__ Mb,
    __half* __restrict__ O) {
    extern __shared__ char dsm[];
    const uint32_t base = smem_u32(dsm);

    const int b = blockIdx.z, h = blockIdx.y;
    const int q0 = blockIdx.x * 64;
    const int tid = threadIdx.x, lane = tid & 31, warp = tid >> 5;
    const int g = lane >> 2, t2 = (lane & 3) * 2;

    // Prologue: stage Q in stage-0 buffer, read A fragments.
    {
        __half* sQ = (__half*)(dsm);
        for (int idx = tid; idx < 512; idx += 128) {
            int r = idx >> 3, c = (idx & 7) * 8;
            size_t go = (size_t)(b * SEQ + q0 + r) * DM + h * HD + c;
            *(uint4*)(sQ + r * LDA + c) = *(const uint4*)(Q + go);
        }
    }
    __syncthreads();
    uint32_t qh[4][4];
    {
        int arow = warp * 16 + (lane & 15);
#pragma unroll
        for (int kk = 0; kk < 4; kk++) {
            int acol = kk * 16 + (lane >> 4) * 8;
            ldm4(qh[kk], base + (uint32_t)arow * (LDA * 2) + acol * 2);
        }
    }
    __syncthreads();

    // Stage load: K + V, 2 planes x 64 rows x 8 x 16B = 1024 chunks, 8/thread.
#define A_LOAD(s, kt)                                                           \
    {                                                                           \
        uint32_t sb = base + (uint32_t)(s) * ASTG;                              \
        const __half* gsrc[2] = { K, V };                                       \
        _Pragma("unroll")                                                       \
        for (int i = 0; i < 8; i++) {                                           \
            int id = tid + i * 128;                                             \
            int ar = id >> 9, cid = id & 511;                                   \
            int r = cid >> 3, ch = cid & 7;                                     \
            cpa16(sb + ar * APLN + r * (LDA * 2) + ch * 16,                     \
                  gsrc[ar] + (size_t)(b * SEQ + (kt) * 64 + r) * DM + h * HD + ch * 8); \
        }                                                                       \
        cpa_commit();                                                           \
    }

    float oa[8][4];
#pragma unroll
    for (int j = 0; j < 8; j++)
#pragma unroll
        for (int v = 0; v < 4; v++) oa[j][v] = 0.f;
    float mx0 = -INFINITY, mx1 = -INFINITY, l0 = 0.f, l1 = 0.f;

    const uint32_t* mr0 = Mb + (size_t)(b * SEQ + q0 + warp * 16 + g) * (SEQ / 32);
    const uint32_t* mr1 = mr0 + 8 * (SEQ / 32);

    A_LOAD(0, 0);

    for (int kt = 0; kt < SEQ / 64; kt++) {
        if (kt + 1 < SEQ / 64) { A_LOAD((kt + 1) & 1, kt + 1); cpa_wait1(); }
        else                   { cpa_wait0(); }
        __syncthreads();

        const uint32_t sK = base + (uint32_t)(kt & 1) * ASTG;
        const uint32_t sV = sK + APLN;

        // S = Q K^T
        float s[8][4];
#pragma unroll
        for (int j = 0; j < 8; j++)
#pragma unroll
            for (int v = 0; v < 4; v++) s[j][v] = 0.f;
#pragma unroll
        for (int kk = 0; kk < 4; kk++) {
            uint32_t bh[4][4];
            const int bro = (lane & 7) + (lane >> 4) * 8;
            const int bco = kk * 16 + ((lane >> 3) & 1) * 8;
#pragma unroll
            for (int j2 = 0; j2 < 4; j2++)
                ldm4(bh[j2], sK + (uint32_t)(j2 * 16 + bro) * (LDA * 2) + bco * 2);
#pragma unroll
            for (int j = 0; j < 8; j++)
                mma16816(s[j], qh[kk], &bh[j >> 1][(j & 1) * 2]);
        }

        // Mask
        uint32_t w0a = mr0[kt * 2], w0b = mr0[kt * 2 + 1];
        uint32_t w1a = mr1[kt * 2], w1b = mr1[kt * 2 + 1];
#pragma unroll
        for (int j = 0; j < 8; j++) {
            uint32_t wr0 = (j < 4) ? w0a : w0b;
            uint32_t wr1 = (j < 4) ? w1a : w1b;
            int sh = (j * 8 + t2) & 31;
            if (!((wr0 >> sh) & 1u))       s[j][0] = -1e20f;
            if (!((wr0 >> (sh + 1)) & 1u)) s[j][1] = -1e20f;
            if (!((wr1 >> sh) & 1u))       s[j][2] = -1e20f;
            if (!((wr1 >> (sh + 1)) & 1u)) s[j][3] = -1e20f;
        }

        // Online softmax
        float tm0 = s[0][0], tm1 = s[0][2];
#pragma unroll
        for (int j = 0; j < 8; j++) {
            tm0 = fmaxf(tm0, fmaxf(s[j][0], s[j][1]));
            tm1 = fmaxf(tm1, fmaxf(s[j][2], s[j][3]));
        }
        tm0 = fmaxf(tm0, __shfl_xor_sync(0xffffffffu, tm0, 1));
        tm0 = fmaxf(tm0, __shfl_xor_sync(0xffffffffu, tm0, 2));
        tm1 = fmaxf(tm1, __shfl_xor_sync(0xffffffffu, tm1, 1));
        tm1 = fmaxf(tm1, __shfl_xor_sync(0xffffffffu, tm1, 2));
        float nm0 = fmaxf(mx0, tm0), nm1 = fmaxf(mx1, tm1);
        float cr0 = __expf(mx0 - nm0), cr1 = __expf(mx1 - nm1);
        mx0 = nm0; mx1 = nm1;

        float ps0 = 0.f, ps1 = 0.f;
#pragma unroll
        for (int j = 0; j < 8; j++) {
            s[j][0] = __expf(s[j][0] - nm0); ps0 += s[j][0];
            s[j][1] = __expf(s[j][1] - nm0); ps0 += s[j][1];
            s[j][2] = __expf(s[j][2] - nm1); ps1 += s[j][2];
            s[j][3] = __expf(s[j][3] - nm1); ps1 += s[j][3];
        }
        ps0 += __shfl_xor_sync(0xffffffffu, ps0, 1);
        ps0 += __shfl_xor_sync(0xffffffffu, ps0, 2);
        ps1 += __shfl_xor_sync(0xffffffffu, ps1, 1);
        ps1 += __shfl_xor_sync(0xffffffffu, ps1, 2);
        l0 = l0 * cr0 + ps0;
        l1 = l1 * cr1 + ps1;
#pragma unroll
        for (int j = 0; j < 8; j++) {
            oa[j][0] *= cr0; oa[j][1] *= cr0;
            oa[j][2] *= cr1; oa[j][3] *= cr1;
        }

        // P -> fp16 A-fragments
        uint32_t ph[4][4];
#pragma unroll
        for (int s4 = 0; s4 < 4; s4++) {
            int ta = 2 * s4, tb = ta + 1;
            ph[s4][0] = h2pack(s[ta][0], s[ta][1]);
            ph[s4][1] = h2pack(s[ta][2], s[ta][3]);
            ph[s4][2] = h2pack(s[tb][0], s[tb][1]);
            ph[s4][3] = h2pack(s[tb][2], s[tb][3]);
        }

        // O += P V
#pragma unroll
        for (int s4 = 0; s4 < 4; s4++) {
            uint32_t vh[4][4];
            const int vrow = s4 * 16 + ((lane >> 3) & 1) * 8 + (lane & 7);
#pragma unroll
            for (int n2 = 0; n2 < 4; n2++) {
                int vcol = n2 * 16 + (lane >> 4) * 8;
                ldm4t(vh[n2], sV + (uint32_t)vrow * (LDA * 2) + vcol * 2);
            }
#pragma unroll
            for (int j = 0; j < 8; j++)
                mma16816(oa[j], ph[s4], &vh[j >> 1][(j & 1) * 2]);
        }
        __syncthreads();
    }

    float il0 = 1.f / l0, il1 = 1.f / l1;
    int row0 = b * SEQ + q0 + warp * 16 + g;
    size_t b0 = (size_t)row0 * DM + h * HD;
    size_t b1 = b0 + (size_t)8 * DM;
#pragma unroll
    for (int j = 0; j < 8; j++) {
        *(uint32_t*)(O + b0 + j * 8 + t2) = h2pack(oa[j][0] * il0, oa[j][1] * il0);
        *(uint32_t*)(O + b1 + j * 8 + t2) = h2pack(oa[j][2] * il1, oa[j][3] * il1);
    }
#undef A_LOAD
}

// ---------------------------------------------------------------------------
extern "C" void kernel_launch(void* const* d_in, const int* in_sizes, int n_in,
                              void* d_out, int out_size) {
    const float* query = (const float*)d_in[0];
    const float* key_t = (const float*)d_in[1];
    const float* value = (const float*)d_in[2];
    const int*   mask  = (const int*)d_in[3];
    const float* wq    = (const float*)d_in[4];
    const float* wk    = (const float*)d_in[5];
    const float* wv    = (const float*)d_in[6];
    const float* wo    = (const float*)d_in[7];
    float* out = (float*)d_out;

    __half *iQ, *iK, *iV, *wqh, *wkh, *wvh, *woh, *Qp, *Kp, *Vp, *Op;
    uint32_t* Mb;
    cudaGetSymbolAddress((void**)&iQ, g_iQ);   cudaGetSymbolAddress((void**)&iK, g_iK);
    cudaGetSymbolAddress((void**)&iV, g_iV);
    cudaGetSymbolAddress((void**)&wqh, g_wq);  cudaGetSymbolAddress((void**)&wkh, g_wk);
    cudaGetSymbolAddress((void**)&wvh, g_wv);  cudaGetSymbolAddress((void**)&woh, g_wo);
    cudaGetSymbolAddress((void**)&Qp, g_Q);    cudaGetSymbolAddress((void**)&Kp, g_K);
    cudaGetSymbolAddress((void**)&Vp, g_V);    cudaGetSymbolAddress((void**)&Op, g_O);
    cudaGetSymbolAddress((void**)&Mb, g_Mb);

    static bool attr_set = false;
    if (!attr_set) {
        cudaFuncSetAttribute(gemm_fp16<1>, cudaFuncAttributeMaxDynamicSharedMemorySize, GDSM);
        cudaFuncSetAttribute(gemm_fp16<0>, cudaFuncAttributeMaxDynamicSharedMemorySize, GDSM);
        cudaFuncSetAttribute(attn_fp16,    cudaFuncAttributeMaxDynamicSharedMemorySize, ADSM);
        attr_set = true;
    }

    pack_mask<<<MWORDS * 32 / 256, 256>>>(mask, Mb);

    conv_hi<<<NTOK * DM / 1024, 256>>>(query, iQ);
    conv_hi<<<NTOK * DM / 1024, 256>>>(key_t, iK);
    conv_hi<<<NTOK * DM / 1024, 256>>>(value, iV);
    conv_hi<<<DM * DM / 1024, 256>>>(wq, wqh);
    conv_hi<<<DM * DM / 1024, 256>>>(wk, wkh);
    conv_hi<<<DM * DM / 1024, 256>>>(wv, wvh);
    conv_hi<<<DM * DM / 1024, 256>>>(wo, woh);

    dim3 gg(DM / 128, NTOK / 128);   // (8, 32)
    gemm_fp16<1><<<gg, 256, GDSM>>>(iQ, wqh, nullptr, Qp, 0.125f);
    gemm_fp16<1><<<gg, 256, GDSM>>>(iK, wkh, nullptr, Kp, 1.0f);
    gemm_fp16<1><<<gg, 256, GDSM>>>(iV, wvh, nullptr, Vp, 1.0f);

    dim3 ga(SEQ / 64, NH, BATCH);    // (32, 16, 2)
    attn_fp16<<<ga, 128, ADSM>>>(Qp, Kp, Vp, Mb, Op);

    gemm_fp16<0><<<gg, 256, GDSM>>>(Op, woh, out, nullptr, 1.0f);
}

// round 8
// speedup vs baseline: 6.6371x; 1.0732x over previous
#include <cuda_runtime.h>
#include <cuda_fp16.h>
#include <math.h>
#include <stdint.h>

#define DM   1024
#define HD   64
#define NH   16
#define BATCH 2
#define SEQ  2048
#define NTOK (BATCH*SEQ)
#define MWORDS (BATCH*SEQ*SEQ/32)

// ---------------------------------------------------------------------------
// Scratch (no allocations allowed).  Pure fp16 pipeline.
// ---------------------------------------------------------------------------
__device__ __half g_iQ[NTOK*DM], g_iK[NTOK*DM], g_iV[NTOK*DM];
__device__ __half g_wq[DM*DM], g_wk[DM*DM], g_wv[DM*DM], g_wo[DM*DM];
__device__ __half g_Q[NTOK*DM], g_K[NTOK*DM], g_V[NTOK*DM];
__device__ __half g_O[NTOK*DM];
__device__ uint32_t g_Mb[MWORDS];

// ---------------------------------------------------------------------------
// Helpers
// ---------------------------------------------------------------------------
__device__ __forceinline__ uint32_t smem_u32(const void* p) {
    uint32_t a;
    asm("{ .reg .u64 t; cvta.to.shared.u64 t, %1; cvt.u32.u64 %0, t; }" : "=r"(a) : "l"(p));
    return a;
}
__device__ __forceinline__ uint32_t h2pack(float lo, float hi) {
    __half2 t = __floats2half2_rn(lo, hi);
    return *reinterpret_cast<uint32_t*>(&t);
}
__device__ __forceinline__ void ldm4(uint32_t* r, uint32_t addr) {
    asm volatile("ldmatrix.sync.aligned.m8n8.x4.shared.b16 {%0,%1,%2,%3}, [%4];"
                 : "=r"(r[0]), "=r"(r[1]), "=r"(r[2]), "=r"(r[3]) : "r"(addr));
}
__device__ __forceinline__ void ldm4t(uint32_t* r, uint32_t addr) {
    asm volatile("ldmatrix.sync.aligned.m8n8.x4.trans.shared.b16 {%0,%1,%2,%3}, [%4];"
                 : "=r"(r[0]), "=r"(r[1]), "=r"(r[2]), "=r"(r[3]) : "r"(addr));
}
__device__ __forceinline__ void mma16816(float* c, const uint32_t* a, const uint32_t* b) {
    asm volatile(
        "mma.sync.aligned.m16n8k16.row.col.f32.f16.f16.f32 "
        "{%0,%1,%2,%3}, {%4,%5,%6,%7}, {%8,%9}, {%0,%1,%2,%3};\n"
        : "+f"(c[0]), "+f"(c[1]), "+f"(c[2]), "+f"(c[3])
        : "r"(a[0]), "r"(a[1]), "r"(a[2]), "r"(a[3]), "r"(b[0]), "r"(b[1]));
}
__device__ __forceinline__ void cpa16(uint32_t dst, const void* src) {
    asm volatile("cp.async.cg.shared.global [%0], [%1], 16;" :: "r"(dst), "l"(src) : "memory");
}
__device__ __forceinline__ void cpa_commit() { asm volatile("cp.async.commit_group;" ::: "memory"); }
__device__ __forceinline__ void cpa_wait1()  { asm volatile("cp.async.wait_group 1;" ::: "memory"); }
__device__ __forceinline__ void cpa_wait0()  { asm volatile("cp.async.wait_group 0;" ::: "memory"); }

// ---------------------------------------------------------------------------
// Mask -> bitmask (int4 loads, nibble + shfl-OR assembly; 1 word per 8 lanes)
// ---------------------------------------------------------------------------
__global__ __launch_bounds__(256) void pack_mask(const int* __restrict__ mask,
                                                 uint32_t* __restrict__ bits) {
    int t = blockIdx.x * 256 + threadIdx.x;       // elems 4t..4t+3
    int4 m = ((const int4*)mask)[t];
    uint32_t nib = (m.x != 0 ? 1u : 0u) | (m.y != 0 ? 2u : 0u) |
                   (m.z != 0 ? 4u : 0u) | (m.w != 0 ? 8u : 0u);
    uint32_t v = nib << ((threadIdx.x & 7) * 4);
    v |= __shfl_xor_sync(0xffffffffu, v, 1);
    v |= __shfl_xor_sync(0xffffffffu, v, 2);
    v |= __shfl_xor_sync(0xffffffffu, v, 4);
    if ((threadIdx.x & 7) == 0) bits[t >> 3] = v;
}

// ---------------------------------------------------------------------------
// fp32 -> fp16 (2 x float4 per thread)
// ---------------------------------------------------------------------------
__global__ __launch_bounds__(256) void conv_hi(const float* __restrict__ x,
                                               __half* __restrict__ xh) {
    int t = (blockIdx.x * 256 + threadIdx.x) * 2;
    float4 a = ((const float4*)x)[t];
    float4 c = ((const float4*)x)[t + 1];
    ((uint2*)xh)[t]     = make_uint2(h2pack(a.x, a.y), h2pack(a.z, a.w));
    ((uint2*)xh)[t + 1] = make_uint2(h2pack(c.x, c.y), h2pack(c.z, c.w));
}

// ---------------------------------------------------------------------------
// fp16 GEMM body:  C[m][n] = sum_k A[m][k]*B[n][k]  (both K-major, K=1024)
// Tile 128x128, BK=32, 3-stage cp.async pipeline (one sync/iter), 8 warps.
// MODE 1: fp16 C (scaled).  MODE 0: fp32 C.
// ---------------------------------------------------------------------------
#define LDSg 40                 // fp16 row stride (80B), conflict-free ldmatrix
#define PSTG (128*LDSg*2)       // 10240 B per plane
#define SSTG (2*PSTG)           // 20480 B per stage (A, B)
#define GDSM (3*SSTG)           // 61440 B dynamic smem (3 stages)

template<int MODE>
__device__ __forceinline__ void gemm_body(const __half* __restrict__ A,
                                          const __half* __restrict__ B,
                                          float* __restrict__ C,
                                          __half* __restrict__ Ch, float scale) {
    extern __shared__ char dsm[];
    const uint32_t base = smem_u32(dsm);
    const int tid = threadIdx.x, lane = tid & 31, warp = tid >> 5;
    const int wm = (warp & 1) * 64;
    const int wn = (warp >> 1) * 32;
    const int bm = blockIdx.y * 128;
    const int bn = blockIdx.x * 128;

    const __half* gp[2] = { A + (size_t)bm * DM, B + (size_t)bn * DM };

    float acc[4][4][4];
#pragma unroll
    for (int i = 0; i < 4; i++)
#pragma unroll
        for (int j = 0; j < 4; j++)
#pragma unroll
            for (int v = 0; v < 4; v++) acc[i][j][v] = 0.f;

#define G_LOAD(s, k0)                                                           \
    {                                                                           \
        uint32_t sb = base + (uint32_t)(s) * SSTG;                              \
        _Pragma("unroll")                                                       \
        for (int i = 0; i < 4; i++) {                                           \
            int id = tid + i * 256;                                             \
            int pl = id >> 9, cid = id & 511;                                   \
            int r = cid >> 2, ch = cid & 3;                                     \
            cpa16(sb + pl * PSTG + r * (LDSg * 2) + ch * 16,                    \
                  gp[pl] + (size_t)r * DM + (k0) + ch * 8);                     \
        }                                                                       \
        cpa_commit();                                                           \
    }

    G_LOAD(0, 0);
    G_LOAD(1, 32);

    for (int kt = 0; kt < 32; kt++) {
        if (kt < 31) cpa_wait1(); else cpa_wait0();
        __syncthreads();
        if (kt + 2 < 32) G_LOAD((kt + 2) % 3, (kt + 2) * 32);

        const uint32_t sb = base + (uint32_t)(kt % 3) * SSTG;
        const uint32_t sA = sb, sB = sb + PSTG;

#pragma unroll
        for (int kk = 0; kk < 2; kk++) {
            uint32_t ah[4][4], bh[2][4];
            const int acol = kk * 16 + (lane >> 4) * 8;
#pragma unroll
            for (int i = 0; i < 4; i++) {
                int arow = wm + i * 16 + (lane & 15);
                ldm4(ah[i], sA + (uint32_t)arow * (LDSg * 2) + acol * 2);
            }
            const int bcol = kk * 16 + ((lane >> 3) & 1) * 8;
            const int brow_off = (lane & 7) + (lane >> 4) * 8;
#pragma unroll
            for (int j2 = 0; j2 < 2; j2++) {
                int brow = wn + j2 * 16 + brow_off;
                ldm4(bh[j2], sB + (uint32_t)brow * (LDSg * 2) + bcol * 2);
            }
#pragma unroll
            for (int i = 0; i < 4; i++)
#pragma unroll
                for (int j = 0; j < 4; j++)
                    mma16816(acc[i][j], ah[i], &bh[j >> 1][(j & 1) * 2]);
        }
    }

    const int g  = lane >> 2;
    const int t2 = (lane & 3) * 2;
#pragma unroll
    for (int i = 0; i < 4; i++)
#pragma unroll
        for (int j = 0; j < 4; j++) {
            int row = bm + wm + i * 16 + g;
            int col = bn + wn + j * 8 + t2;
            size_t i0 = (size_t)row * DM + col;
            size_t i1 = (size_t)(row + 8) * DM + col;
            float v0 = acc[i][j][0] * scale, v1 = acc[i][j][1] * scale;
            float v2 = acc[i][j][2] * scale, v3 = acc[i][j][3] * scale;
            if (MODE == 0) {
                *(float2*)(C + i0) = make_float2(v0, v1);
                *(float2*)(C + i1) = make_float2(v2, v3);
            } else {
                *(uint32_t*)(Ch + i0) = h2pack(v0, v1);
                *(uint32_t*)(Ch + i1) = h2pack(v2, v3);
            }
        }
#undef G_LOAD
}

// Batched projection GEMM (z = 0:Q, 1:K, 2:V) and output GEMM.
__global__ __launch_bounds__(256, 2) void gemm_proj(
    const __half* __restrict__ iQ, const __half* __restrict__ iK,
    const __half* __restrict__ iV,
    const __half* __restrict__ wq, const __half* __restrict__ wk,
    const __half* __restrict__ wv,
    __half* __restrict__ Qo, __half* __restrict__ Ko, __half* __restrict__ Vo) {
    const __half* A; const __half* B; __half* Ch; float scale = 1.0f;
    if (blockIdx.z == 0)      { A = iQ; B = wq; Ch = Qo; scale = 0.125f; }
    else if (blockIdx.z == 1) { A = iK; B = wk; Ch = Ko; }
    else                      { A = iV; B = wv; Ch = Vo; }
    gemm_body<1>(A, B, nullptr, Ch, scale);
}
__global__ __launch_bounds__(256, 2) void gemm_out(
    const __half* __restrict__ O, const __half* __restrict__ wo,
    float* __restrict__ out) {
    gemm_body<0>(O, wo, out, nullptr, 1.0f);
}

// ---------------------------------------------------------------------------
// fp16 flash attention.  128 q-rows per CTA (two 64-row subtiles sharing the
// staged K/V fragments), 4 warps, 3-stage cp.async K/V pipeline.
// Q pre-scaled by 1/8.
// ---------------------------------------------------------------------------
#define LDA 72                   // fp16 row stride (144B), conflict-free
#define APLN (64*LDA*2)          // 9216 B per plane
#define ASTG (2*APLN)            // 18432 B per stage (K, V)
#define ADSM (3*ASTG)            // 55296 B dynamic smem (3 stages)

__global__ __launch_bounds__(128, 2) void attn_fp16(
    const __half* __restrict__ Q, const __half* __restrict__ K,
    const __half* __restrict__ V, const uint32_t* __restrict__ Mb,
    __half* __restrict__ O) {
    extern __shared__ char dsm[];
    const uint32_t base = smem_u32(dsm);

    const int b = blockIdx.z, h = blockIdx.y;
    const int q0 = blockIdx.x * 128;
    const int tid = threadIdx.x, lane = tid & 31, warp = tid >> 5;
    const int g = lane >> 2, t2 = (lane & 3) * 2;

    // Prologue: stage 128 Q rows into stage-0/1 area, read A fragments.
    {
        __half* sQ = (__half*)(dsm);
        for (int idx = tid; idx < 1024; idx += 128) {
            int r = idx >> 3, c = (idx & 7) * 8;
            size_t go = (size_t)(b * SEQ + q0 + r) * DM + h * HD + c;
            *(uint4*)(sQ + r * LDA + c) = *(const uint4*)(Q + go);
        }
    }
    __syncthreads();
    uint32_t qh[2][4][4];
#pragma unroll
    for (int t = 0; t < 2; t++) {
        int arow = t * 64 + warp * 16 + (lane & 15);
#pragma unroll
        for (int kk = 0; kk < 4; kk++) {
            int acol = kk * 16 + (lane >> 4) * 8;
            ldm4(qh[t][kk], base + (uint32_t)arow * (LDA * 2) + acol * 2);
        }
    }
    __syncthreads();

#define A_LOAD(s, kt)                                                           \
    {                                                                           \
        uint32_t sb = base + (uint32_t)(s) * ASTG;                              \
        const __half* gsrc[2] = { K, V };                                       \
        _Pragma("unroll")                                                       \
        for (int i = 0; i < 8; i++) {                                           \
            int id = tid + i * 128;                                             \
            int ar = id >> 9, cid = id & 511;                                   \
            int r = cid >> 3, ch = cid & 7;                                     \
            cpa16(sb + ar * APLN + r * (LDA * 2) + ch * 16,                     \
                  gsrc[ar] + (size_t)(b * SEQ + (kt) * 64 + r) * DM + h * HD + ch * 8); \
        }                                                                       \
        cpa_commit();                                                           \
    }

    float oa[2][8][4];
#pragma unroll
    for (int t = 0; t < 2; t++)
#pragma unroll
        for (int j = 0; j < 8; j++)
#pragma unroll
            for (int v = 0; v < 4; v++) oa[t][j][v] = 0.f;
    float mx[2][2] = {{-INFINITY, -INFINITY}, {-INFINITY, -INFINITY}};
    float ll[2][2] = {{0.f, 0.f}, {0.f, 0.f}};

    const uint32_t* mr[2][2];
#pragma unroll
    for (int t = 0; t < 2; t++) {
        mr[t][0] = Mb + (size_t)(b * SEQ + q0 + t * 64 + warp * 16 + g) * (SEQ / 32);
        mr[t][1] = mr[t][0] + 8 * (SEQ / 32);
    }

    A_LOAD(0, 0);
    A_LOAD(1, 1);

    for (int kt = 0; kt < SEQ / 64; kt++) {
        if (kt < SEQ / 64 - 1) cpa_wait1(); else cpa_wait0();
        __syncthreads();
        if (kt + 2 < SEQ / 64) A_LOAD((kt + 2) % 3, kt + 2);

        const uint32_t sK = base + (uint32_t)(kt % 3) * ASTG;
        const uint32_t sV = sK + APLN;

        // S = Q K^T for both subtiles, sharing K fragments.
        float s[2][8][4];
#pragma unroll
        for (int t = 0; t < 2; t++)
#pragma unroll
            for (int j = 0; j < 8; j++)
#pragma unroll
                for (int v = 0; v < 4; v++) s[t][j][v] = 0.f;
#pragma unroll
        for (int kk = 0; kk < 4; kk++) {
            uint32_t bh[4][4];
            const int bro = (lane & 7) + (lane >> 4) * 8;
            const int bco = kk * 16 + ((lane >> 3) & 1) * 8;
#pragma unroll
            for (int j2 = 0; j2 < 4; j2++)
                ldm4(bh[j2], sK + (uint32_t)(j2 * 16 + bro) * (LDA * 2) + bco * 2);
#pragma unroll
            for (int t = 0; t < 2; t++)
#pragma unroll
                for (int j = 0; j < 8; j++)
                    mma16816(s[t][j], qh[t][kk], &bh[j >> 1][(j & 1) * 2]);
        }

        // Mask + online softmax + P repack per subtile.
        uint32_t ph[2][4][4];
#pragma unroll
        for (int t = 0; t < 2; t++) {
            uint32_t w0a = mr[t][0][kt * 2], w0b = mr[t][0][kt * 2 + 1];
            uint32_t w1a = mr[t][1][kt * 2], w1b = mr[t][1][kt * 2 + 1];
#pragma unroll
            for (int j = 0; j < 8; j++) {
                uint32_t wr0 = (j < 4) ? w0a : w0b;
                uint32_t wr1 = (j < 4) ? w1a : w1b;
                int sh = (j * 8 + t2) & 31;
                if (!((wr0 >> sh) & 1u))       s[t][j][0] = -1e20f;
                if (!((wr0 >> (sh + 1)) & 1u)) s[t][j][1] = -1e20f;
                if (!((wr1 >> sh) & 1u))       s[t][j][2] = -1e20f;
                if (!((wr1 >> (sh + 1)) & 1u)) s[t][j][3] = -1e20f;
            }

            float tm0 = s[t][0][0], tm1 = s[t][0][2];
#pragma unroll
            for (int j = 0; j < 8; j++) {
                tm0 = fmaxf(tm0, fmaxf(s[t][j][0], s[t][j][1]));
                tm1 = fmaxf(tm1, fmaxf(s[t][j][2], s[t][j][3]));
            }
            tm0 = fmaxf(tm0, __shfl_xor_sync(0xffffffffu, tm0, 1));
            tm0 = fmaxf(tm0, __shfl_xor_sync(0xffffffffu, tm0, 2));
            tm1 = fmaxf(tm1, __shfl_xor_sync(0xffffffffu, tm1, 1));
            tm1 = fmaxf(tm1, __shfl_xor_sync(0xffffffffu, tm1, 2));
            float nm0 = fmaxf(mx[t][0], tm0), nm1 = fmaxf(mx[t][1], tm1);
            float cr0 = __expf(mx[t][0] - nm0), cr1 = __expf(mx[t][1] - nm1);
            mx[t][0] = nm0; mx[t][1] = nm1;

            float ps0 = 0.f, ps1 = 0.f;
#pragma unroll
            for (int j = 0; j < 8; j++) {
                s[t][j][0] = __expf(s[t][j][0] - nm0); ps0 += s[t][j][0];
                s[t][j][1] = __expf(s[t][j][1] - nm0); ps0 += s[t][j][1];
                s[t][j][2] = __expf(s[t][j][2] - nm1); ps1 += s[t][j][2];
                s[t][j][3] = __expf(s[t][j][3] - nm1); ps1 += s[t][j][3];
            }
            ps0 += __shfl_xor_sync(0xffffffffu, ps0, 1);
            ps0 += __shfl_xor_sync(0xffffffffu, ps0, 2);
            ps1 += __shfl_xor_sync(0xffffffffu, ps1, 1);
            ps1 += __shfl_xor_sync(0xffffffffu, ps1, 2);
            ll[t][0] = ll[t][0] * cr0 + ps0;
            ll[t][1] = ll[t][1] * cr1 + ps1;
#pragma unroll
            for (int j = 0; j < 8; j++) {
                oa[t][j][0] *= cr0; oa[t][j][1] *= cr0;
                oa[t][j][2] *= cr1; oa[t][j][3] *= cr1;
            }
#pragma unroll
            for (int s4 = 0; s4 < 4; s4++) {
                int ta = 2 * s4, tb = ta + 1;
                ph[t][s4][0] = h2pack(s[t][ta][0], s[t][ta][1]);
                ph[t][s4][1] = h2pack(s[t][ta][2], s[t][ta][3]);
                ph[t][s4][2] = h2pack(s[t][tb][0], s[t][tb][1]);
                ph[t][s4][3] = h2pack(s[t][tb][2], s[t][tb][3]);
            }
        }

        // O += P V for both subtiles, sharing V fragments.
#pragma unroll
        for (int s4 = 0; s4 < 4; s4++) {
            uint32_t vh[4][4];
            const int vrow = s4 * 16 + ((lane >> 3) & 1) * 8 + (lane & 7);
#pragma unroll
            for (int n2 = 0; n2 < 4; n2++) {
                int vcol = n2 * 16 + (lane >> 4) * 8;
                ldm4t(vh[n2], sV + (uint32_t)vrow * (LDA * 2) + vcol * 2);
            }
#pragma unroll
            for (int t = 0; t < 2; t++)
#pragma unroll
                for (int j = 0; j < 8; j++)
                    mma16816(oa[t][j], ph[t][s4], &vh[j >> 1][(j & 1) * 2]);
        }
    }

#pragma unroll
    for (int t = 0; t < 2; t++) {
        float il0 = 1.f / ll[t][0], il1 = 1.f / ll[t][1];
        int row0 = b * SEQ + q0 + t * 64 + warp * 16 + g;
        size_t b0 = (size_t)row0 * DM + h * HD;
        size_t b1 = b0 + (size_t)8 * DM;
#pragma unroll
        for (int j = 0; j < 8; j++) {
            *(uint32_t*)(O + b0 + j * 8 + t2) = h2pack(oa[t][j][0] * il0, oa[t][j][1] * il0);
            *(uint32_t*)(O + b1 + j * 8 + t2) = h2pack(oa[t][j][2] * il1, oa[t][j][3] * il1);
        }
    }
#undef A_LOAD
}

// ---------------------------------------------------------------------------
extern "C" void kernel_launch(void* const* d_in, const int* in_sizes, int n_in,
                              void* d_out, int out_size) {
    const float* query = (const float*)d_in[0];
    const float* key_t = (const float*)d_in[1];
    const float* value = (const float*)d_in[2];
    const int*   mask  = (const int*)d_in[3];
    const float* wq    = (const float*)d_in[4];
    const float* wk    = (const float*)d_in[5];
    const float* wv    = (const float*)d_in[6];
    const float* wo    = (const float*)d_in[7];
    float* out = (float*)d_out;

    __half *iQ, *iK, *iV, *wqh, *wkh, *wvh, *woh, *Qp, *Kp, *Vp, *Op;
    uint32_t* Mb;
    cudaGetSymbolAddress((void**)&iQ, g_iQ);   cudaGetSymbolAddress((void**)&iK, g_iK);
    cudaGetSymbolAddress((void**)&iV, g_iV);
    cudaGetSymbolAddress((void**)&wqh, g_wq);  cudaGetSymbolAddress((void**)&wkh, g_wk);
    cudaGetSymbolAddress((void**)&wvh, g_wv);  cudaGetSymbolAddress((void**)&woh, g_wo);
    cudaGetSymbolAddress((void**)&Qp, g_Q);    cudaGetSymbolAddress((void**)&Kp, g_K);
    cudaGetSymbolAddress((void**)&Vp, g_V);    cudaGetSymbolAddress((void**)&Op, g_O);
    cudaGetSymbolAddress((void**)&Mb, g_Mb);

    static bool attr_set = false;
    if (!attr_set) {
        cudaFuncSetAttribute(gemm_proj, cudaFuncAttributeMaxDynamicSharedMemorySize, GDSM);
        cudaFuncSetAttribute(gemm_out,  cudaFuncAttributeMaxDynamicSharedMemorySize, GDSM);
        cudaFuncSetAttribute(attn_fp16, cudaFuncAttributeMaxDynamicSharedMemorySize, ADSM);
        attr_set = true;
    }

    pack_mask<<<MWORDS * 8 / 256, 256>>>(mask, Mb);

    conv_hi<<<NTOK * DM / 2048, 256>>>(query, iQ);
    conv_hi<<<NTOK * DM / 2048, 256>>>(key_t, iK);
    conv_hi<<<NTOK * DM / 2048, 256>>>(value, iV);
    conv_hi<<<DM * DM / 2048, 256>>>(wq, wqh);
    conv_hi<<<DM * DM / 2048, 256>>>(wk, wkh);
    conv_hi<<<DM * DM / 2048, 256>>>(wv, wvh);
    conv_hi<<<DM * DM / 2048, 256>>>(wo, woh);

    dim3 gp3(DM / 128, NTOK / 128, 3);   // (8, 32, 3)
    gemm_proj<<<gp3, 256, GDSM>>>(iQ, iK, iV, wqh, wkh, wvh, Qp, Kp, Vp);

    dim3 ga(SEQ / 128, NH, BATCH);       // (16, 16, 2)
    attn_fp16<<<ga, 128, ADSM>>>(Qp, Kp, Vp, Mb, Op);

    dim3 gg(DM / 128, NTOK / 128);       // (8, 32)
    gemm_out<<<gg, 256, GDSM>>>(Op, woh, out);
}

// round 9
// speedup vs baseline: 6.9552x; 1.0479x over previous
#include <cuda_runtime.h>
#include <cuda_fp16.h>
#include <math.h>
#include <stdint.h>

#define DM   1024
#define HD   64
#define NH   16
#define BATCH 2
#define SEQ  2048
#define NTOK (BATCH*SEQ)
#define MWORDS (BATCH*SEQ*SEQ/32)

// ---------------------------------------------------------------------------
// Scratch (no allocations allowed).  Pure fp16 pipeline.
// ---------------------------------------------------------------------------
__device__ __half g_iQ[NTOK*DM], g_iK[NTOK*DM], g_iV[NTOK*DM];
__device__ __half g_wq[DM*DM], g_wk[DM*DM], g_wv[DM*DM], g_wo[DM*DM];
__device__ __half g_Q[NTOK*DM], g_K[NTOK*DM], g_V[NTOK*DM];
__device__ __half g_O[NTOK*DM];
__device__ uint32_t g_Mb[MWORDS];

// ---------------------------------------------------------------------------
// Helpers
// ---------------------------------------------------------------------------
__device__ __forceinline__ uint32_t smem_u32(const void* p) {
    uint32_t a;
    asm("{ .reg .u64 t; cvta.to.shared.u64 t, %1; cvt.u32.u64 %0, t; }" : "=r"(a) : "l"(p));
    return a;
}
__device__ __forceinline__ uint32_t h2pack(float lo, float hi) {
    __half2 t = __floats2half2_rn(lo, hi);
    return *reinterpret_cast<uint32_t*>(&t);
}
__device__ __forceinline__ void ldm4(uint32_t* r, uint32_t addr) {
    asm volatile("ldmatrix.sync.aligned.m8n8.x4.shared.b16 {%0,%1,%2,%3}, [%4];"
                 : "=r"(r[0]), "=r"(r[1]), "=r"(r[2]), "=r"(r[3]) : "r"(addr));
}
__device__ __forceinline__ void ldm4t(uint32_t* r, uint32_t addr) {
    asm volatile("ldmatrix.sync.aligned.m8n8.x4.trans.shared.b16 {%0,%1,%2,%3}, [%4];"
                 : "=r"(r[0]), "=r"(r[1]), "=r"(r[2]), "=r"(r[3]) : "r"(addr));
}
__device__ __forceinline__ void mma16816(float* c, const uint32_t* a, const uint32_t* b) {
    asm volatile(
        "mma.sync.aligned.m16n8k16.row.col.f32.f16.f16.f32 "
        "{%0,%1,%2,%3}, {%4,%5,%6,%7}, {%8,%9}, {%0,%1,%2,%3};\n"
        : "+f"(c[0]), "+f"(c[1]), "+f"(c[2]), "+f"(c[3])
        : "r"(a[0]), "r"(a[1]), "r"(a[2]), "r"(a[3]), "r"(b[0]), "r"(b[1]));
}
__device__ __forceinline__ void cpa16(uint32_t dst, const void* src) {
    asm volatile("cp.async.cg.shared.global [%0], [%1], 16;" :: "r"(dst), "l"(src) : "memory");
}
__device__ __forceinline__ void cpa_commit() { asm volatile("cp.async.commit_group;" ::: "memory"); }
__device__ __forceinline__ void cpa_wait2()  { asm volatile("cp.async.wait_group 2;" ::: "memory"); }
__device__ __forceinline__ void cpa_wait1()  { asm volatile("cp.async.wait_group 1;" ::: "memory"); }
__device__ __forceinline__ void cpa_wait0()  { asm volatile("cp.async.wait_group 0;" ::: "memory"); }

// ---------------------------------------------------------------------------
// Fused prep: 7 fp32->fp16 conversions + mask bitpack, one launch.
// Region sizes are multiples of 256 so no block straddles regions.
// ---------------------------------------------------------------------------
#define IN_U  (NTOK*DM/4)          // 1048576 float4 units per input array
#define W_U   (DM*DM/4)            // 262144 per weight
#define CONV_UNITS (3*IN_U + 4*W_U) // 4194304
#define MASK_UNITS (BATCH*SEQ*SEQ/4) // 2097152 int4 units
#define PREP_BLOCKS ((CONV_UNITS + MASK_UNITS) / 256)

__global__ __launch_bounds__(256) void prep_all(
    const float* __restrict__ q, const float* __restrict__ k,
    const float* __restrict__ v,
    const float* __restrict__ wq, const float* __restrict__ wk,
    const float* __restrict__ wv, const float* __restrict__ wo,
    const int* __restrict__ mask,
    __half* __restrict__ iQ, __half* __restrict__ iK, __half* __restrict__ iV,
    __half* __restrict__ wqh, __half* __restrict__ wkh,
    __half* __restrict__ wvh, __half* __restrict__ woh,
    uint32_t* __restrict__ bits) {
    int idx = blockIdx.x * 256 + threadIdx.x;
    if (idx < CONV_UNITS) {
        const float* src; __half* dst; int off;
        if (idx < 3 * IN_U) {
            int arr = idx >> 20;            // / IN_U
            off = idx & (IN_U - 1);
            src = arr == 0 ? q : arr == 1 ? k : v;
            dst = arr == 0 ? iQ : arr == 1 ? iK : iV;
        } else {
            int w = idx - 3 * IN_U;
            int arr = w >> 18;              // / W_U
            off = w & (W_U - 1);
            src = arr == 0 ? wq : arr == 1 ? wk : arr == 2 ? wv : wo;
            dst = arr == 0 ? wqh : arr == 1 ? wkh : arr == 2 ? wvh : woh;
        }
        float4 a = ((const float4*)src)[off];
        ((uint2*)dst)[off] = make_uint2(h2pack(a.x, a.y), h2pack(a.z, a.w));
    } else {
        int t = idx - CONV_UNITS;           // int4 unit; (t & 7) == (threadIdx.x & 7)
        int4 m = ((const int4*)mask)[t];
        uint32_t nib = (m.x != 0 ? 1u : 0u) | (m.y != 0 ? 2u : 0u) |
                       (m.z != 0 ? 4u : 0u) | (m.w != 0 ? 8u : 0u);
        uint32_t vv = nib << ((threadIdx.x & 7) * 4);
        vv |= __shfl_xor_sync(0xffffffffu, vv, 1);
        vv |= __shfl_xor_sync(0xffffffffu, vv, 2);
        vv |= __shfl_xor_sync(0xffffffffu, vv, 4);
        if ((threadIdx.x & 7) == 0) bits[t >> 3] = vv;
    }
}

// ---------------------------------------------------------------------------
// fp16 GEMM body:  C[m][n] = sum_k A[m][k]*B[n][k]  (both K-major, K=1024)
// Tile 128x128, BK=32, 4-stage cp.async pipeline (one sync/iter), 8 warps.
// MODE 1: fp16 C (scaled).  MODE 0: fp32 C.
// ---------------------------------------------------------------------------
#define LDSg 40                 // fp16 row stride (80B), conflict-free ldmatrix
#define PSTG (128*LDSg*2)       // 10240 B per plane
#define SSTG (2*PSTG)           // 20480 B per stage (A, B)
#define GDSM (4*SSTG)           // 81920 B dynamic smem (4 stages)

template<int MODE>
__device__ __forceinline__ void gemm_body(const __half* __restrict__ A,
                                          const __half* __restrict__ B,
                                          float* __restrict__ C,
                                          __half* __restrict__ Ch, float scale) {
    extern __shared__ char dsm[];
    const uint32_t base = smem_u32(dsm);
    const int tid = threadIdx.x, lane = tid & 31, warp = tid >> 5;
    const int wm = (warp & 1) * 64;
    const int wn = (warp >> 1) * 32;
    const int bm = blockIdx.y * 128;
    const int bn = blockIdx.x * 128;

    const __half* gp[2] = { A + (size_t)bm * DM, B + (size_t)bn * DM };

    float acc[4][4][4];
#pragma unroll
    for (int i = 0; i < 4; i++)
#pragma unroll
        for (int j = 0; j < 4; j++)
#pragma unroll
            for (int v = 0; v < 4; v++) acc[i][j][v] = 0.f;

#define G_LOAD(s, k0)                                                           \
    {                                                                           \
        uint32_t sb = base + (uint32_t)(s) * SSTG;                              \
        _Pragma("unroll")                                                       \
        for (int i = 0; i < 4; i++) {                                           \
            int id = tid + i * 256;                                             \
            int pl = id >> 9, cid = id & 511;                                   \
            int r = cid >> 2, ch = cid & 3;                                     \
            cpa16(sb + pl * PSTG + r * (LDSg * 2) + ch * 16,                    \
                  gp[pl] + (size_t)r * DM + (k0) + ch * 8);                     \
        }                                                                       \
        cpa_commit();                                                           \
    }

    G_LOAD(0, 0);
    G_LOAD(1, 32);
    G_LOAD(2, 64);

    for (int kt = 0; kt < 32; kt++) {
        if (kt < 30)       cpa_wait2();
        else if (kt == 30) cpa_wait1();
        else               cpa_wait0();
        __syncthreads();
        if (kt + 3 < 32) G_LOAD((kt + 3) & 3, (kt + 3) * 32);

        const uint32_t sb = base + (uint32_t)(kt & 3) * SSTG;
        const uint32_t sA = sb, sB = sb + PSTG;

#pragma unroll
        for (int kk = 0; kk < 2; kk++) {
            uint32_t ah[4][4], bh[2][4];
            const int acol = kk * 16 + (lane >> 4) * 8;
#pragma unroll
            for (int i = 0; i < 4; i++) {
                int arow = wm + i * 16 + (lane & 15);
                ldm4(ah[i], sA + (uint32_t)arow * (LDSg * 2) + acol * 2);
            }
            const int bcol = kk * 16 + ((lane >> 3) & 1) * 8;
            const int brow_off = (lane & 7) + (lane >> 4) * 8;
#pragma unroll
            for (int j2 = 0; j2 < 2; j2++) {
                int brow = wn + j2 * 16 + brow_off;
                ldm4(bh[j2], sB + (uint32_t)brow * (LDSg * 2) + bcol * 2);
            }
#pragma unroll
            for (int i = 0; i < 4; i++)
#pragma unroll
                for (int j = 0; j < 4; j++)
                    mma16816(acc[i][j], ah[i], &bh[j >> 1][(j & 1) * 2]);
        }
    }

    const int g  = lane >> 2;
    const int t2 = (lane & 3) * 2;
#pragma unroll
    for (int i = 0; i < 4; i++)
#pragma unroll
        for (int j = 0; j < 4; j++) {
            int row = bm + wm + i * 16 + g;
            int col = bn + wn + j * 8 + t2;
            size_t i0 = (size_t)row * DM + col;
            size_t i1 = (size_t)(row + 8) * DM + col;
            float v0 = acc[i][j][0] * scale, v1 = acc[i][j][1] * scale;
            float v2 = acc[i][j][2] * scale, v3 = acc[i][j][3] * scale;
            if (MODE == 0) {
                *(float2*)(C + i0) = make_float2(v0, v1);
                *(float2*)(C + i1) = make_float2(v2, v3);
            } else {
                *(uint32_t*)(Ch + i0) = h2pack(v0, v1);
                *(uint32_t*)(Ch + i1) = h2pack(v2, v3);
            }
        }
#undef G_LOAD
}

// Batched projection GEMM (z = 0:Q, 1:K, 2:V) and output GEMM.
__global__ __launch_bounds__(256, 2) void gemm_proj(
    const __half* __restrict__ iQ, const __half* __restrict__ iK,
    const __half* __restrict__ iV,
    const __half* __restrict__ wq, const __half* __restrict__ wk,
    const __half* __restrict__ wv,
    __half* __restrict__ Qo, __half* __restrict__ Ko, __half* __restrict__ Vo) {
    const __half* A; const __half* B; __half* Ch; float scale = 1.0f;
    if (blockIdx.z == 0)      { A = iQ; B = wq; Ch = Qo; scale = 0.125f; }
    else if (blockIdx.z == 1) { A = iK; B = wk; Ch = Ko; }
    else                      { A = iV; B = wv; Ch = Vo; }
    gemm_body<1>(A, B, nullptr, Ch, scale);
}
__global__ __launch_bounds__(256, 2) void gemm_out(
    const __half* __restrict__ O, const __half* __restrict__ wo,
    float* __restrict__ out) {
    gemm_body<0>(O, wo, out, nullptr, 1.0f);
}

// ---------------------------------------------------------------------------
// fp16 flash attention.  128 q-rows per CTA (two 64-row subtiles sharing the
// staged K/V fragments), 4 warps, 4-stage cp.async K/V pipeline.
// Q pre-scaled by 1/8.
// ---------------------------------------------------------------------------
#define LDA 72                   // fp16 row stride (144B), conflict-free
#define APLN (64*LDA*2)          // 9216 B per plane
#define ASTG (2*APLN)            // 18432 B per stage (K, V)
#define ADSM (4*ASTG)            // 73728 B dynamic smem (4 stages)
#define NKT  (SEQ/64)            // 32

__global__ __launch_bounds__(128, 2) void attn_fp16(
    const __half* __restrict__ Q, const __half* __restrict__ K,
    const __half* __restrict__ V, const uint32_t* __restrict__ Mb,
    __half* __restrict__ O) {
    extern __shared__ char dsm[];
    const uint32_t base = smem_u32(dsm);

    const int b = blockIdx.z, h = blockIdx.y;
    const int q0 = blockIdx.x * 128;
    const int tid = threadIdx.x, lane = tid & 31, warp = tid >> 5;
    const int g = lane >> 2, t2 = (lane & 3) * 2;

    // Prologue: stage 128 Q rows into stage-0/1 area, read A fragments.
    {
        __half* sQ = (__half*)(dsm);
        for (int idx = tid; idx < 1024; idx += 128) {
            int r = idx >> 3, c = (idx & 7) * 8;
            size_t go = (size_t)(b * SEQ + q0 + r) * DM + h * HD + c;
            *(uint4*)(sQ + r * LDA + c) = *(const uint4*)(Q + go);
        }
    }
    __syncthreads();
    uint32_t qh[2][4][4];
#pragma unroll
    for (int t = 0; t < 2; t++) {
        int arow = t * 64 + warp * 16 + (lane & 15);
#pragma unroll
        for (int kk = 0; kk < 4; kk++) {
            int acol = kk * 16 + (lane >> 4) * 8;
            ldm4(qh[t][kk], base + (uint32_t)arow * (LDA * 2) + acol * 2);
        }
    }
    __syncthreads();

#define A_LOAD(s, kt)                                                           \
    {                                                                           \
        uint32_t sb = base + (uint32_t)(s) * ASTG;                              \
        const __half* gsrc[2] = { K, V };                                       \
        _Pragma("unroll")                                                       \
        for (int i = 0; i < 8; i++) {                                           \
            int id = tid + i * 128;                                             \
            int ar = id >> 9, cid = id & 511;                                   \
            int r = cid >> 3, ch = cid & 7;                                     \
            cpa16(sb + ar * APLN + r * (LDA * 2) + ch * 16,                     \
                  gsrc[ar] + (size_t)(b * SEQ + (kt) * 64 + r) * DM + h * HD + ch * 8); \
        }                                                                       \
        cpa_commit();                                                           \
    }

    float oa[2][8][4];
#pragma unroll
    for (int t = 0; t < 2; t++)
#pragma unroll
        for (int j = 0; j < 8; j++)
#pragma unroll
            for (int v = 0; v < 4; v++) oa[t][j][v] = 0.f;
    float mx[2][2] = {{-INFINITY, -INFINITY}, {-INFINITY, -INFINITY}};
    float ll[2][2] = {{0.f, 0.f}, {0.f, 0.f}};

    const uint32_t* mr[2][2];
#pragma unroll
    for (int t = 0; t < 2; t++) {
        mr[t][0] = Mb + (size_t)(b * SEQ + q0 + t * 64 + warp * 16 + g) * (SEQ / 32);
        mr[t][1] = mr[t][0] + 8 * (SEQ / 32);
    }

    A_LOAD(0, 0);
    A_LOAD(1, 1);
    A_LOAD(2, 2);

    for (int kt = 0; kt < NKT; kt++) {
        if (kt < NKT - 2)       cpa_wait2();
        else if (kt == NKT - 2) cpa_wait1();
        else                    cpa_wait0();
        __syncthreads();
        if (kt + 3 < NKT) A_LOAD((kt + 3) & 3, kt + 3);

        const uint32_t sK = base + (uint32_t)(kt & 3) * ASTG;
        const uint32_t sV = sK + APLN;

        // S = Q K^T for both subtiles, sharing K fragments.
        float s[2][8][4];
#pragma unroll
        for (int t = 0; t < 2; t++)
#pragma unroll
            for (int j = 0; j < 8; j++)
#pragma unroll
                for (int v = 0; v < 4; v++) s[t][j][v] = 0.f;
#pragma unroll
        for (int kk = 0; kk < 4; kk++) {
            uint32_t bh[4][4];
            const int bro = (lane & 7) + (lane >> 4) * 8;
            const int bco = kk * 16 + ((lane >> 3) & 1) * 8;
#pragma unroll
            for (int j2 = 0; j2 < 4; j2++)
                ldm4(bh[j2], sK + (uint32_t)(j2 * 16 + bro) * (LDA * 2) + bco * 2);
#pragma unroll
            for (int t = 0; t < 2; t++)
#pragma unroll
                for (int j = 0; j < 8; j++)
                    mma16816(s[t][j], qh[t][kk], &bh[j >> 1][(j & 1) * 2]);
        }

        // Mask + online softmax + P repack per subtile.
        uint32_t ph[2][4][4];
#pragma unroll
        for (int t = 0; t < 2; t++) {
            uint32_t w0a = mr[t][0][kt * 2], w0b = mr[t][0][kt * 2 + 1];
            uint32_t w1a = mr[t][1][kt * 2], w1b = mr[t][1][kt * 2 + 1];
#pragma unroll
            for (int j = 0; j < 8; j++) {
                uint32_t wr0 = (j < 4) ? w0a : w0b;
                uint32_t wr1 = (j < 4) ? w1a : w1b;
                int sh = (j * 8 + t2) & 31;
                if (!((wr0 >> sh) & 1u))       s[t][j][0] = -1e20f;
                if (!((wr0 >> (sh + 1)) & 1u)) s[t][j][1] = -1e20f;
                if (!((wr1 >> sh) & 1u))       s[t][j][2] = -1e20f;
                if (!((wr1 >> (sh + 1)) & 1u)) s[t][j][3] = -1e20f;
            }

            float tm0 = s[t][0][0], tm1 = s[t][0][2];
#pragma unroll
            for (int j = 0; j < 8; j++) {
                tm0 = fmaxf(tm0, fmaxf(s[t][j][0], s[t][j][1]));
                tm1 = fmaxf(tm1, fmaxf(s[t][j][2], s[t][j][3]));
            }
            tm0 = fmaxf(tm0, __shfl_xor_sync(0xffffffffu, tm0, 1));
            tm0 = fmaxf(tm0, __shfl_xor_sync(0xffffffffu, tm0, 2));
            tm1 = fmaxf(tm1, __shfl_xor_sync(0xffffffffu, tm1, 1));
            tm1 = fmaxf(tm1, __shfl_xor_sync(0xffffffffu, tm1, 2));
            float nm0 = fmaxf(mx[t][0], tm0), nm1 = fmaxf(mx[t][1], tm1);
            float cr0 = __expf(mx[t][0] - nm0), cr1 = __expf(mx[t][1] - nm1);
            mx[t][0] = nm0; mx[t][1] = nm1;

            float ps0 = 0.f, ps1 = 0.f;
#pragma unroll
            for (int j = 0; j < 8; j++) {
                s[t][j][0] = __expf(s[t][j][0] - nm0); ps0 += s[t][j][0];
                s[t][j][1] = __expf(s[t][j][1] - nm0); ps0 += s[t][j][1];
                s[t][j][2] = __expf(s[t][j][2] - nm1); ps1 += s[t][j][2];
                s[t][j][3] = __expf(s[t][j][3] - nm1); ps1 += s[t][j][3];
            }
            ps0 += __shfl_xor_sync(0xffffffffu, ps0, 1);
            ps0 += __shfl_xor_sync(0xffffffffu, ps0, 2);
            ps1 += __shfl_xor_sync(0xffffffffu, ps1, 1);
            ps1 += __shfl_xor_sync(0xffffffffu, ps1, 2);
            ll[t][0] = ll[t][0] * cr0 + ps0;
            ll[t][1] = ll[t][1] * cr1 + ps1;
#pragma unroll
            for (int j = 0; j < 8; j++) {
                oa[t][j][0] *= cr0; oa[t][j][1] *= cr0;
                oa[t][j][2] *= cr1; oa[t][j][3] *= cr1;
            }
#pragma unroll
            for (int s4 = 0; s4 < 4; s4++) {
                int ta = 2 * s4, tb = ta + 1;
                ph[t][s4][0] = h2pack(s[t][ta][0], s[t][ta][1]);
                ph[t][s4][1] = h2pack(s[t][ta][2], s[t][ta][3]);
                ph[t][s4][2] = h2pack(s[t][tb][0], s[t][tb][1]);
                ph[t][s4][3] = h2pack(s[t][tb][2], s[t][tb][3]);
            }
        }

        // O += P V for both subtiles, sharing V fragments.
#pragma unroll
        for (int s4 = 0; s4 < 4; s4++) {
            uint32_t vh[4][4];
            const int vrow = s4 * 16 + ((lane >> 3) & 1) * 8 + (lane & 7);
#pragma unroll
            for (int n2 = 0; n2 < 4; n2++) {
                int vcol = n2 * 16 + (lane >> 4) * 8;
                ldm4t(vh[n2], sV + (uint32_t)vrow * (LDA * 2) + vcol * 2);
            }
#pragma unroll
            for (int t = 0; t < 2; t++)
#pragma unroll
                for (int j = 0; j < 8; j++)
                    mma16816(oa[t][j], ph[t][s4], &vh[j >> 1][(j & 1) * 2]);
        }
    }

#pragma unroll
    for (int t = 0; t < 2; t++) {
        float il0 = 1.f / ll[t][0], il1 = 1.f / ll[t][1];
        int row0 = b * SEQ + q0 + t * 64 + warp * 16 + g;
        size_t b0 = (size_t)row0 * DM + h * HD;
        size_t b1 = b0 + (size_t)8 * DM;
#pragma unroll
        for (int j = 0; j < 8; j++) {
            *(uint32_t*)(O + b0 + j * 8 + t2) = h2pack(oa[t][j][0] * il0, oa[t][j][1] * il0);
            *(uint32_t*)(O + b1 + j * 8 + t2) = h2pack(oa[t][j][2] * il1, oa[t][j][3] * il1);
        }
    }
#undef A_LOAD
}

// ---------------------------------------------------------------------------
extern "C" void kernel_launch(void* const* d_in, const int* in_sizes, int n_in,
                              void* d_out, int out_size) {
    const float* query = (const float*)d_in[0];
    const float* key_t = (const float*)d_in[1];
    const float* value = (const float*)d_in[2];
    const int*   mask  = (const int*)d_in[3];
    const float* wq    = (const float*)d_in[4];
    const float* wk    = (const float*)d_in[5];
    const float* wv    = (const float*)d_in[6];
    const float* wo    = (const float*)d_in[7];
    float* out = (float*)d_out;

    __half *iQ, *iK, *iV, *wqh, *wkh, *wvh, *woh, *Qp, *Kp, *Vp, *Op;
    uint32_t* Mb;
    cudaGetSymbolAddress((void**)&iQ, g_iQ);   cudaGetSymbolAddress((void**)&iK, g_iK);
    cudaGetSymbolAddress((void**)&iV, g_iV);
    cudaGetSymbolAddress((void**)&wqh, g_wq);  cudaGetSymbolAddress((void**)&wkh, g_wk);
    cudaGetSymbolAddress((void**)&wvh, g_wv);  cudaGetSymbolAddress((void**)&woh, g_wo);
    cudaGetSymbolAddress((void**)&Qp, g_Q);    cudaGetSymbolAddress((void**)&Kp, g_K);
    cudaGetSymbolAddress((void**)&Vp, g_V);    cudaGetSymbolAddress((void**)&Op, g_O);
    cudaGetSymbolAddress((void**)&Mb, g_Mb);

    static bool attr_set = false;
    if (!attr_set) {
        cudaFuncSetAttribute(gemm_proj, cudaFuncAttributeMaxDynamicSharedMemorySize, GDSM);
        cudaFuncSetAttribute(gemm_out,  cudaFuncAttributeMaxDynamicSharedMemorySize, GDSM);
        cudaFuncSetAttribute(attn_fp16, cudaFuncAttributeMaxDynamicSharedMemorySize, ADSM);
        attr_set = true;
    }

    prep_all<<<PREP_BLOCKS, 256>>>(query, key_t, value, wq, wk, wv, wo, mask,
                                   iQ, iK, iV, wqh, wkh, wvh, woh, Mb);

    dim3 gp3(DM / 128, NTOK / 128, 3);   // (8, 32, 3)
    gemm_proj<<<gp3, 256, GDSM>>>(iQ, iK, iV, wqh, wkh, wvh, Qp, Kp, Vp);

    dim3 ga(SEQ / 128, NH, BATCH);       // (16, 16, 2)
    attn_fp16<<<ga, 128, ADSM>>>(Qp, Kp, Vp, Mb, Op);

    dim3 gg(DM / 128, NTOK / 128);       // (8, 32)
    gemm_out<<<gg, 256, GDSM>>>(Op, woh, out);
}

// round 10
// speedup vs baseline: 7.3359x; 1.0547x over previous
#include <cuda_runtime.h>
#include <cuda_fp16.h>
#include <math.h>
#include <stdint.h>

#define DM   1024
#define HD   64
#define NH   16
#define BATCH 2
#define SEQ  2048
#define NTOK (BATCH*SEQ)
#define MWORDS (BATCH*SEQ*SEQ/32)

// ---------------------------------------------------------------------------
// Scratch (no allocations allowed).  Pure fp16 pipeline.
// ---------------------------------------------------------------------------
__device__ __half g_iQ[NTOK*DM], g_iK[NTOK*DM], g_iV[NTOK*DM];
__device__ __half g_wq[DM*DM], g_wk[DM*DM], g_wv[DM*DM], g_wo[DM*DM];
__device__ __half g_Q[NTOK*DM], g_K[NTOK*DM], g_V[NTOK*DM];
__device__ __half g_O[NTOK*DM];
__device__ uint32_t g_Mb[MWORDS];

// ---------------------------------------------------------------------------
// Helpers
// ---------------------------------------------------------------------------
__device__ __forceinline__ uint32_t smem_u32(const void* p) {
    uint32_t a;
    asm("{ .reg .u64 t; cvta.to.shared.u64 t, %1; cvt.u32.u64 %0, t; }" : "=r"(a) : "l"(p));
    return a;
}
__device__ __forceinline__ uint32_t h2pack(float lo, float hi) {
    __half2 t = __floats2half2_rn(lo, hi);
    return *reinterpret_cast<uint32_t*>(&t);
}
__device__ __forceinline__ void ldm4(uint32_t* r, uint32_t addr) {
    asm volatile("ldmatrix.sync.aligned.m8n8.x4.shared.b16 {%0,%1,%2,%3}, [%4];"
                 : "=r"(r[0]), "=r"(r[1]), "=r"(r[2]), "=r"(r[3]) : "r"(addr));
}
__device__ __forceinline__ void ldm4t(uint32_t* r, uint32_t addr) {
    asm volatile("ldmatrix.sync.aligned.m8n8.x4.trans.shared.b16 {%0,%1,%2,%3}, [%4];"
                 : "=r"(r[0]), "=r"(r[1]), "=r"(r[2]), "=r"(r[3]) : "r"(addr));
}
__device__ __forceinline__ void mma16816(float* c, const uint32_t* a, const uint32_t* b) {
    asm volatile(
        "mma.sync.aligned.m16n8k16.row.col.f32.f16.f16.f32 "
        "{%0,%1,%2,%3}, {%4,%5,%6,%7}, {%8,%9}, {%0,%1,%2,%3};\n"
        : "+f"(c[0]), "+f"(c[1]), "+f"(c[2]), "+f"(c[3])
        : "r"(a[0]), "r"(a[1]), "r"(a[2]), "r"(a[3]), "r"(b[0]), "r"(b[1]));
}
__device__ __forceinline__ void cpa16(uint32_t dst, const void* src) {
    asm volatile("cp.async.cg.shared.global [%0], [%1], 16;" :: "r"(dst), "l"(src) : "memory");
}
__device__ __forceinline__ void cpa_commit() { asm volatile("cp.async.commit_group;" ::: "memory"); }
__device__ __forceinline__ void cpa_wait3()  { asm volatile("cp.async.wait_group 3;" ::: "memory"); }
__device__ __forceinline__ void cpa_wait2()  { asm volatile("cp.async.wait_group 2;" ::: "memory"); }
__device__ __forceinline__ void cpa_wait1()  { asm volatile("cp.async.wait_group 1;" ::: "memory"); }
__device__ __forceinline__ void cpa_wait0()  { asm volatile("cp.async.wait_group 0;" ::: "memory"); }

// ---------------------------------------------------------------------------
// Fused prep: 7 fp32->fp16 conversions + mask bitpack, one launch.
// ---------------------------------------------------------------------------
#define IN_U  (NTOK*DM/4)
#define W_U   (DM*DM/4)
#define CONV_UNITS (3*IN_U + 4*W_U)
#define MASK_UNITS (BATCH*SEQ*SEQ/4)
#define PREP_BLOCKS ((CONV_UNITS + MASK_UNITS) / 256)

__global__ __launch_bounds__(256) void prep_all(
    const float* __restrict__ q, const float* __restrict__ k,
    const float* __restrict__ v,
    const float* __restrict__ wq, const float* __restrict__ wk,
    const float* __restrict__ wv, const float* __restrict__ wo,
    const int* __restrict__ mask,
    __half* __restrict__ iQ, __half* __restrict__ iK, __half* __restrict__ iV,
    __half* __restrict__ wqh, __half* __restrict__ wkh,
    __half* __restrict__ wvh, __half* __restrict__ woh,
    uint32_t* __restrict__ bits) {
    int idx = blockIdx.x * 256 + threadIdx.x;
    if (idx < CONV_UNITS) {
        const float* src; __half* dst; int off;
        if (idx < 3 * IN_U) {
            int arr = idx >> 20;
            off = idx & (IN_U - 1);
            src = arr == 0 ? q : arr == 1 ? k : v;
            dst = arr == 0 ? iQ : arr == 1 ? iK : iV;
        } else {
            int w = idx - 3 * IN_U;
            int arr = w >> 18;
            off = w & (W_U - 1);
            src = arr == 0 ? wq : arr == 1 ? wk : arr == 2 ? wv : wo;
            dst = arr == 0 ? wqh : arr == 1 ? wkh : arr == 2 ? wvh : woh;
        }
        float4 a = ((const float4*)src)[off];
        ((uint2*)dst)[off] = make_uint2(h2pack(a.x, a.y), h2pack(a.z, a.w));
    } else {
        int t = idx - CONV_UNITS;
        int4 m = ((const int4*)mask)[t];
        uint32_t nib = (m.x != 0 ? 1u : 0u) | (m.y != 0 ? 2u : 0u) |
                       (m.z != 0 ? 4u : 0u) | (m.w != 0 ? 8u : 0u);
        uint32_t vv = nib << ((threadIdx.x & 7) * 4);
        vv |= __shfl_xor_sync(0xffffffffu, vv, 1);
        vv |= __shfl_xor_sync(0xffffffffu, vv, 2);
        vv |= __shfl_xor_sync(0xffffffffu, vv, 4);
        if ((threadIdx.x & 7) == 0) bits[t >> 3] = vv;
    }
}

// ---------------------------------------------------------------------------
// fp16 GEMM body:  C[m][n] = sum_k A[m][k]*B[n][k]  (both K-major, K=1024)
// Tile 128x128, BK=32, 5-stage cp.async pipeline, 4 warps (2m x 2n),
// warp tile 64x64 (32 MMAs per kk on 8 LDSM).
// MODE 1: fp16 C (scaled).  MODE 0: fp32 C.
// ---------------------------------------------------------------------------
#define LDSg 40                 // fp16 row stride (80B), conflict-free ldmatrix
#define PSTG (128*LDSg*2)       // 10240 B per plane
#define SSTG (2*PSTG)           // 20480 B per stage (A, B)
#define GNST 5
#define GDSM (GNST*SSTG)        // 102400 B dynamic smem

template<int MODE>
__device__ __forceinline__ void gemm_body(const __half* __restrict__ A,
                                          const __half* __restrict__ B,
                                          float* __restrict__ C,
                                          __half* __restrict__ Ch, float scale) {
    extern __shared__ char dsm[];
    const uint32_t base = smem_u32(dsm);
    const int tid = threadIdx.x, lane = tid & 31, warp = tid >> 5;
    const int wm = (warp & 1) * 64;
    const int wn = (warp >> 1) * 64;
    const int bm = blockIdx.y * 128;
    const int bn = blockIdx.x * 128;

    const __half* gp[2] = { A + (size_t)bm * DM, B + (size_t)bn * DM };

    float acc[4][8][4];
#pragma unroll
    for (int i = 0; i < 4; i++)
#pragma unroll
        for (int j = 0; j < 8; j++)
#pragma unroll
            for (int v = 0; v < 4; v++) acc[i][j][v] = 0.f;

    // Stage load: 2 planes x 128 rows x 4 x 16B chunks = 1024 chunks, 8/thread.
#define G_LOAD(s, k0)                                                           \
    {                                                                           \
        uint32_t sb = base + (uint32_t)(s) * SSTG;                              \
        _Pragma("unroll")                                                       \
        for (int i = 0; i < 8; i++) {                                           \
            int id = tid + i * 128;                                             \
            int pl = id >> 9, cid = id & 511;                                   \
            int r = cid >> 2, ch = cid & 3;                                     \
            cpa16(sb + pl * PSTG + r * (LDSg * 2) + ch * 16,                    \
                  gp[pl] + (size_t)r * DM + (k0) + ch * 8);                     \
        }                                                                       \
        cpa_commit();                                                           \
    }

    G_LOAD(0, 0);
    G_LOAD(1, 32);
    G_LOAD(2, 64);
    G_LOAD(3, 96);

    for (int kt = 0; kt < 32; kt++) {
        int rem = 31 - kt;
        if (rem >= 3)      cpa_wait3();
        else if (rem == 2) cpa_wait2();
        else if (rem == 1) cpa_wait1();
        else               cpa_wait0();
        __syncthreads();
        if (kt + 4 < 32) G_LOAD((kt + 4) % GNST, (kt + 4) * 32);

        const uint32_t sb = base + (uint32_t)(kt % GNST) * SSTG;
        const uint32_t sA = sb, sB = sb + PSTG;

#pragma unroll
        for (int kk = 0; kk < 2; kk++) {
            uint32_t ah[4][4], bh[4][4];
            const int acol = kk * 16 + (lane >> 4) * 8;
#pragma unroll
            for (int i = 0; i < 4; i++) {
                int arow = wm + i * 16 + (lane & 15);
                ldm4(ah[i], sA + (uint32_t)arow * (LDSg * 2) + acol * 2);
            }
            const int bcol = kk * 16 + ((lane >> 3) & 1) * 8;
            const int brow_off = (lane & 7) + (lane >> 4) * 8;
#pragma unroll
            for (int j2 = 0; j2 < 4; j2++) {
                int brow = wn + j2 * 16 + brow_off;
                ldm4(bh[j2], sB + (uint32_t)brow * (LDSg * 2) + bcol * 2);
            }
#pragma unroll
            for (int i = 0; i < 4; i++)
#pragma unroll
                for (int j = 0; j < 8; j++)
                    mma16816(acc[i][j], ah[i], &bh[j >> 1][(j & 1) * 2]);
        }
    }

    const int g  = lane >> 2;
    const int t2 = (lane & 3) * 2;
#pragma unroll
    for (int i = 0; i < 4; i++)
#pragma unroll
        for (int j = 0; j < 8; j++) {
            int row = bm + wm + i * 16 + g;
            int col = bn + wn + j * 8 + t2;
            size_t i0 = (size_t)row * DM + col;
            size_t i1 = (size_t)(row + 8) * DM + col;
            float v0 = acc[i][j][0] * scale, v1 = acc[i][j][1] * scale;
            float v2 = acc[i][j][2] * scale, v3 = acc[i][j][3] * scale;
            if (MODE == 0) {
                *(float2*)(C + i0) = make_float2(v0, v1);
                *(float2*)(C + i1) = make_float2(v2, v3);
            } else {
                *(uint32_t*)(Ch + i0) = h2pack(v0, v1);
                *(uint32_t*)(Ch + i1) = h2pack(v2, v3);
            }
        }
#undef G_LOAD
}

// Batched projection GEMM (z = 0:Q, 1:K, 2:V) and output GEMM.
__global__ __launch_bounds__(128, 2) void gemm_proj(
    const __half* __restrict__ iQ, const __half* __restrict__ iK,
    const __half* __restrict__ iV,
    const __half* __restrict__ wq, const __half* __restrict__ wk,
    const __half* __restrict__ wv,
    __half* __restrict__ Qo, __half* __restrict__ Ko, __half* __restrict__ Vo) {
    const __half* A; const __half* B; __half* Ch; float scale = 1.0f;
    if (blockIdx.z == 0)      { A = iQ; B = wq; Ch = Qo; scale = 0.125f; }
    else if (blockIdx.z == 1) { A = iK; B = wk; Ch = Ko; }
    else                      { A = iV; B = wv; Ch = Vo; }
    gemm_body<1>(A, B, nullptr, Ch, scale);
}
__global__ __launch_bounds__(128, 2) void gemm_out(
    const __half* __restrict__ O, const __half* __restrict__ wo,
    float* __restrict__ out) {
    gemm_body<0>(O, wo, out, nullptr, 1.0f);
}

// ---------------------------------------------------------------------------
// fp16 flash attention.  128 q-rows per CTA (two 64-row subtiles sharing the
// staged K/V fragments), 4 warps, 4-stage cp.async K/V pipeline.
// Q pre-scaled by 1/8.  (Unchanged from R9.)
// ---------------------------------------------------------------------------
#define LDA 72                   // fp16 row stride (144B), conflict-free
#define APLN (64*LDA*2)          // 9216 B per plane
#define ASTG (2*APLN)            // 18432 B per stage (K, V)
#define ADSM (4*ASTG)            // 73728 B dynamic smem (4 stages)
#define NKT  (SEQ/64)            // 32

__global__ __launch_bounds__(128, 2) void attn_fp16(
    const __half* __restrict__ Q, const __half* __restrict__ K,
    const __half* __restrict__ V, const uint32_t* __restrict__ Mb,
    __half* __restrict__ O) {
    extern __shared__ char dsm[];
    const uint32_t base = smem_u32(dsm);

    const int b = blockIdx.z, h = blockIdx.y;
    const int q0 = blockIdx.x * 128;
    const int tid = threadIdx.x, lane = tid & 31, warp = tid >> 5;
    const int g = lane >> 2, t2 = (lane & 3) * 2;

    {
        __half* sQ = (__half*)(dsm);
        for (int idx = tid; idx < 1024; idx += 128) {
            int r = idx >> 3, c = (idx & 7) * 8;
            size_t go = (size_t)(b * SEQ + q0 + r) * DM + h * HD + c;
            *(uint4*)(sQ + r * LDA + c) = *(const uint4*)(Q + go);
        }
    }
    __syncthreads();
    uint32_t qh[2][4][4];
#pragma unroll
    for (int t = 0; t < 2; t++) {
        int arow = t * 64 + warp * 16 + (lane & 15);
#pragma unroll
        for (int kk = 0; kk < 4; kk++) {
            int acol = kk * 16 + (lane >> 4) * 8;
            ldm4(qh[t][kk], base + (uint32_t)arow * (LDA * 2) + acol * 2);
        }
    }
    __syncthreads();

#define A_LOAD(s, kt)                                                           \
    {                                                                           \
        uint32_t sb = base + (uint32_t)(s) * ASTG;                              \
        const __half* gsrc[2] = { K, V };                                       \
        _Pragma("unroll")                                                       \
        for (int i = 0; i < 8; i++) {                                           \
            int id = tid + i * 128;                                             \
            int ar = id >> 9, cid = id & 511;                                   \
            int r = cid >> 3, ch = cid & 7;                                     \
            cpa16(sb + ar * APLN + r * (LDA * 2) + ch * 16,                     \
                  gsrc[ar] + (size_t)(b * SEQ + (kt) * 64 + r) * DM + h * HD + ch * 8); \
        }                                                                       \
        cpa_commit();                                                           \
    }

    float oa[2][8][4];
#pragma unroll
    for (int t = 0; t < 2; t++)
#pragma unroll
        for (int j = 0; j < 8; j++)
#pragma unroll
            for (int v = 0; v < 4; v++) oa[t][j][v] = 0.f;
    float mx[2][2] = {{-INFINITY, -INFINITY}, {-INFINITY, -INFINITY}};
    float ll[2][2] = {{0.f, 0.f}, {0.f, 0.f}};

    const uint32_t* mr[2][2];
#pragma unroll
    for (int t = 0; t < 2; t++) {
        mr[t][0] = Mb + (size_t)(b * SEQ + q0 + t * 64 + warp * 16 + g) * (SEQ / 32);
        mr[t][1] = mr[t][0] + 8 * (SEQ / 32);
    }

    A_LOAD(0, 0);
    A_LOAD(1, 1);
    A_LOAD(2, 2);

    for (int kt = 0; kt < NKT; kt++) {
        if (kt < NKT - 2)       cpa_wait2();
        else if (kt == NKT - 2) cpa_wait1();
        else                    cpa_wait0();
        __syncthreads();
        if (kt + 3 < NKT) A_LOAD((kt + 3) & 3, kt + 3);

        const uint32_t sK = base + (uint32_t)(kt & 3) * ASTG;
        const uint32_t sV = sK + APLN;

        float s[2][8][4];
#pragma unroll
        for (int t = 0; t < 2; t++)
#pragma unroll
            for (int j = 0; j < 8; j++)
#pragma unroll
                for (int v = 0; v < 4; v++) s[t][j][v] = 0.f;
#pragma unroll
        for (int kk = 0; kk < 4; kk++) {
            uint32_t bh[4][4];
            const int bro = (lane & 7) + (lane >> 4) * 8;
            const int bco = kk * 16 + ((lane >> 3) & 1) * 8;
#pragma unroll
            for (int j2 = 0; j2 < 4; j2++)
                ldm4(bh[j2], sK + (uint32_t)(j2 * 16 + bro) * (LDA * 2) + bco * 2);
#pragma unroll
            for (int t = 0; t < 2; t++)
#pragma unroll
                for (int j = 0; j < 8; j++)
                    mma16816(s[t][j], qh[t][kk], &bh[j >> 1][(j & 1) * 2]);
        }

        uint32_t ph[2][4][4];
#pragma unroll
        for (int t = 0; t < 2; t++) {
            uint32_t w0a = mr[t][0][kt * 2], w0b = mr[t][0][kt * 2 + 1];
            uint32_t w1a = mr[t][1][kt * 2], w1b = mr[t][1][kt * 2 + 1];
#pragma unroll
            for (int j = 0; j < 8; j++) {
                uint32_t wr0 = (j < 4) ? w0a : w0b;
                uint32_t wr1 = (j < 4) ? w1a : w1b;
                int sh = (j * 8 + t2) & 31;
                if (!((wr0 >> sh) & 1u))       s[t][j][0] = -1e20f;
                if (!((wr0 >> (sh + 1)) & 1u)) s[t][j][1] = -1e20f;
                if (!((wr1 >> sh) & 1u))       s[t][j][2] = -1e20f;
                if (!((wr1 >> (sh + 1)) & 1u)) s[t][j][3] = -1e20f;
            }

            float tm0 = s[t][0][0], tm1 = s[t][0][2];
#pragma unroll
            for (int j = 0; j < 8; j++) {
                tm0 = fmaxf(tm0, fmaxf(s[t][j][0], s[t][j][1]));
                tm1 = fmaxf(tm1, fmaxf(s[t][j][2], s[t][j][3]));
            }
            tm0 = fmaxf(tm0, __shfl_xor_sync(0xffffffffu, tm0, 1));
            tm0 = fmaxf(tm0, __shfl_xor_sync(0xffffffffu, tm0, 2));
            tm1 = fmaxf(tm1, __shfl_xor_sync(0xffffffffu, tm1, 1));
            tm1 = fmaxf(tm1, __shfl_xor_sync(0xffffffffu, tm1, 2));
            float nm0 = fmaxf(mx[t][0], tm0), nm1 = fmaxf(mx[t][1], tm1);
            float cr0 = __expf(mx[t][0] - nm0), cr1 = __expf(mx[t][1] - nm1);
            mx[t][0] = nm0; mx[t][1] = nm1;

            float ps0 = 0.f, ps1 = 0.f;
#pragma unroll
            for (int j = 0; j < 8; j++) {
                s[t][j][0] = __expf(s[t][j][0] - nm0); ps0 += s[t][j][0];
                s[t][j][1] = __expf(s[t][j][1] - nm0); ps0 += s[t][j][1];
                s[t][j][2] = __expf(s[t][j][2] - nm1); ps1 += s[t][j][2];
                s[t][j][3] = __expf(s[t][j][3] - nm1); ps1 += s[t][j][3];
            }
            ps0 += __shfl_xor_sync(0xffffffffu, ps0, 1);
            ps0 += __shfl_xor_sync(0xffffffffu, ps0, 2);
            ps1 += __shfl_xor_sync(0xffffffffu, ps1, 1);
            ps1 += __shfl_xor_sync(0xffffffffu, ps1, 2);
            ll[t][0] = ll[t][0] * cr0 + ps0;
            ll[t][1] = ll[t][1] * cr1 + ps1;
#pragma unroll
            for (int j = 0; j < 8; j++) {
                oa[t][j][0] *= cr0; oa[t][j][1] *= cr0;
                oa[t][j][2] *= cr1; oa[t][j][3] *= cr1;
            }
#pragma unroll
            for (int s4 = 0; s4 < 4; s4++) {
                int ta = 2 * s4, tb = ta + 1;
                ph[t][s4][0] = h2pack(s[t][ta][0], s[t][ta][1]);
                ph[t][s4][1] = h2pack(s[t][ta][2], s[t][ta][3]);
                ph[t][s4][2] = h2pack(s[t][tb][0], s[t][tb][1]);
                ph[t][s4][3] = h2pack(s[t][tb][2], s[t][tb][3]);
            }
        }

#pragma unroll
        for (int s4 = 0; s4 < 4; s4++) {
            uint32_t vh[4][4];
            const int vrow = s4 * 16 + ((lane >> 3) & 1) * 8 + (lane & 7);
#pragma unroll
            for (int n2 = 0; n2 < 4; n2++) {
                int vcol = n2 * 16 + (lane >> 4) * 8;
                ldm4t(vh[n2], sV + (uint32_t)vrow * (LDA * 2) + vcol * 2);
            }
#pragma unroll
            for (int t = 0; t < 2; t++)
#pragma unroll
                for (int j = 0; j < 8; j++)
                    mma16816(oa[t][j], ph[t][s4], &vh[j >> 1][(j & 1) * 2]);
        }
    }

#pragma unroll
    for (int t = 0; t < 2; t++) {
        float il0 = 1.f / ll[t][0], il1 = 1.f / ll[t][1];
        int row0 = b * SEQ + q0 + t * 64 + warp * 16 + g;
        size_t b0 = (size_t)row0 * DM + h * HD;
        size_t b1 = b0 + (size_t)8 * DM;
#pragma unroll
        for (int j = 0; j < 8; j++) {
            *(uint32_t*)(O + b0 + j * 8 + t2) = h2pack(oa[t][j][0] * il0, oa[t][j][1] * il0);
            *(uint32_t*)(O + b1 + j * 8 + t2) = h2pack(oa[t][j][2] * il1, oa[t][j][3] * il1);
        }
    }
#undef A_LOAD
}

// ---------------------------------------------------------------------------
extern "C" void kernel_launch(void* const* d_in, const int* in_sizes, int n_in,
                              void* d_out, int out_size) {
    const float* query = (const float*)d_in[0];
    const float* key_t = (const float*)d_in[1];
    const float* value = (const float*)d_in[2];
    const int*   mask  = (const int*)d_in[3];
    const float* wq    = (const float*)d_in[4];
    const float* wk    = (const float*)d_in[5];
    const float* wv    = (const float*)d_in[6];
    const float* wo    = (const float*)d_in[7];
    float* out = (float*)d_out;

    __half *iQ, *iK, *iV, *wqh, *wkh, *wvh, *woh, *Qp, *Kp, *Vp, *Op;
    uint32_t* Mb;
    cudaGetSymbolAddress((void**)&iQ, g_iQ);   cudaGetSymbolAddress((void**)&iK, g_iK);
    cudaGetSymbolAddress((void**)&iV, g_iV);
    cudaGetSymbolAddress((void**)&wqh, g_wq);  cudaGetSymbolAddress((void**)&wkh, g_wk);
    cudaGetSymbolAddress((void**)&wvh, g_wv);  cudaGetSymbolAddress((void**)&woh, g_wo);
    cudaGetSymbolAddress((void**)&Qp, g_Q);    cudaGetSymbolAddress((void**)&Kp, g_K);
    cudaGetSymbolAddress((void**)&Vp, g_V);    cudaGetSymbolAddress((void**)&Op, g_O);
    cudaGetSymbolAddress((void**)&Mb, g_Mb);

    static bool attr_set = false;
    if (!attr_set) {
        cudaFuncSetAttribute(gemm_proj, cudaFuncAttributeMaxDynamicSharedMemorySize, GDSM);
        cudaFuncSetAttribute(gemm_out,  cudaFuncAttributeMaxDynamicSharedMemorySize, GDSM);
        cudaFuncSetAttribute(attn_fp16, cudaFuncAttributeMaxDynamicSharedMemorySize, ADSM);
        attr_set = true;
    }

    prep_all<<<PREP_BLOCKS, 256>>>(query, key_t, value, wq, wk, wv, wo, mask,
                                   iQ, iK, iV, wqh, wkh, wvh, woh, Mb);

    dim3 gp3(DM / 128, NTOK / 128, 3);   // (8, 32, 3)
    gemm_proj<<<gp3, 128, GDSM>>>(iQ, iK, iV, wqh, wkh, wvh, Qp, Kp, Vp);

    dim3 ga(SEQ / 128, NH, BATCH);       // (16, 16, 2)
    attn_fp16<<<ga, 128, ADSM>>>(Qp, Kp, Vp, Mb, Op);

    dim3 gg(DM / 128, NTOK / 128);       // (8, 32)
    gemm_out<<<gg, 128, GDSM>>>(Op, woh, out);
}